// round 1
// baseline (speedup 1.0000x reference)
#include <cuda_runtime.h>

// ---------------- problem constants ----------------
#define MAXN 50000
#define MAXE 1600000
#define MAXG 1024

// ---------------- device scratch ----------------
__device__ int   g_is64;
__device__ int   g_deg[MAXN];
__device__ int   g_rowptr[MAXN + 1];
__device__ int   g_cursor[MAXN];
__device__ int   g_col[MAXE];
__device__ float g_agg1[MAXN * 32];
__device__ float g_xa[MAXN * 64];
__device__ float g_W1[64 * 384];
__device__ float g_W2[192 * 384];
__device__ float g_t1[(size_t)MAXN * 384];
__device__ float g_h1[(size_t)MAXN * 192];
__device__ float g_t2lin[(size_t)MAXN * 256];
__device__ float g_m2[(size_t)MAXN * 128];
__device__ float g_agg2[(size_t)MAXN * 128];
__device__ float g_h2[(size_t)MAXN * 192];
__device__ float g_pool[MAXG * 384];

// ---------------- index decode (int64 vs int32, runtime-detected) ----------
__device__ __forceinline__ int ld_index(const void* p, long long i) {
    if (g_is64) return (int)((const long long*)p)[i];
    return ((const int*)p)[i];
}

// Detect dtype: int64 little-endian nonneg values < 2^31 have all odd 32-bit
// words zero. For a genuine int32 edge list, odd words are src[1],src[3],...
// uniform in [0,50000): P(all 32 == 0) ~ 0.
__global__ void k_detect(const unsigned int* ei) {
    if (blockIdx.x == 0 && threadIdx.x == 0) {
        int ok = 1;
        for (int i = 1; i < 64; i += 2)
            if (ei[i] != 0u) ok = 0;
        g_is64 = ok;
    }
}

__global__ void k_zero_deg(int n) {
    int i = blockIdx.x * blockDim.x + threadIdx.x;
    if (i < n) g_deg[i] = 0;
}

__global__ void k_hist(const void* ei, int E) {
    int i = blockIdx.x * blockDim.x + threadIdx.x;
    if (i < E) {
        int d = ld_index(ei, (long long)E + i);   // dst row
        atomicAdd(&g_deg[d], 1);
    }
}

// single-block scan of degrees -> rowptr/cursor
__global__ void k_scan(int n) {
    __shared__ int sh[1024];
    __shared__ int carry;
    int tid = threadIdx.x;
    if (tid == 0) carry = 0;
    __syncthreads();
    for (int base = 0; base < n; base += 1024) {
        int i = base + tid;
        int v = (i < n) ? g_deg[i] : 0;
        sh[tid] = v;
        __syncthreads();
        for (int off = 1; off < 1024; off <<= 1) {
            int t = (tid >= off) ? sh[tid - off] : 0;
            __syncthreads();
            sh[tid] += t;
            __syncthreads();
        }
        int excl = sh[tid] - v;
        if (i < n) { g_rowptr[i] = carry + excl; g_cursor[i] = carry + excl; }
        __syncthreads();
        if (tid == 0) carry += sh[1023];
        __syncthreads();
    }
    if (tid == 0) g_rowptr[n] = carry;
}

__global__ void k_fill(const void* ei, int E) {
    int i = blockIdx.x * blockDim.x + threadIdx.x;
    if (i < E) {
        int s = ld_index(ei, i);
        int d = ld_index(ei, (long long)E + i);
        int p = atomicAdd(&g_cursor[d], 1);
        g_col[p] = s;
    }
}

// agg1[v] = sum_{u->v} x[u]   (32 dims; warp per node, lane = feature)
__global__ void k_agg1(const float* __restrict__ x, int N) {
    int w = (blockIdx.x * blockDim.x + threadIdx.x) >> 5;
    int lane = threadIdx.x & 31;
    if (w >= N) return;
    int e0 = g_rowptr[w], e1 = g_rowptr[w + 1];
    float acc = 0.f;
    for (int e = e0; e < e1; e++) {
        int s = g_col[e];
        acc += __ldg(&x[s * 32 + lane]);
    }
    g_agg1[w * 32 + lane] = acc;
}

// xa = [x | agg1]  (N x 64)
__global__ void k_pack_xa(const float* __restrict__ x, int N) {
    int i = blockIdx.x * blockDim.x + threadIdx.x;
    if (i >= N * 64) return;
    int n = i >> 6, k = i & 63;
    g_xa[i] = (k < 32) ? x[n * 32 + k] : g_agg1[n * 32 + (k - 32)];
}

// W1 pack [64 x 384]: cols [0,128)=fc11 (x rows), [128,256)=conv11 (agg rows),
// [256,320)=fc12, [320,384)=fc13
__global__ void k_pack_w1(const float* fc11, const float* conv11,
                          const float* fc12, const float* fc13) {
    int i = blockIdx.x * blockDim.x + threadIdx.x;
    if (i >= 64 * 384) return;
    int k = i / 384, m = i % 384;
    float v = 0.f;
    if (k < 32) {
        if (m < 128)                 v = fc11[k * 128 + m];
        else if (m >= 256 && m < 320) v = fc12[k * 64 + (m - 256)];
        else if (m >= 320)            v = fc13[k * 64 + (m - 320)];
    } else {
        if (m >= 128 && m < 256)      v = conv11[(k - 32) * 128 + (m - 128)];
    }
    g_W1[i] = v;
}

// W2 pack [192 x 384]: [fc21 | conv21 | fc22 | fc23]
__global__ void k_pack_w2(const float* fc21, const float* conv21,
                          const float* fc22, const float* fc23) {
    int i = blockIdx.x * blockDim.x + threadIdx.x;
    if (i >= 192 * 384) return;
    int k = i / 384, m = i % 384;
    float v;
    if (m < 128)      v = fc21[k * 128 + m];
    else if (m < 256) v = conv21[k * 128 + (m - 128)];
    else if (m < 320) v = fc22[k * 64 + (m - 256)];
    else              v = fc23[k * 64 + (m - 320)];
    g_W2[i] = v;
}

// ---------------- tiled fp32 GEMM: C[N,384] = A[N,K] @ W[K,384] ----------
// MODE 1: A=g_xa (K=64),  store -> g_t1[n*384+m]
// MODE 2: A=g_h1 (K=192), store -> g_t2lin (lin cols) / g_m2 (conv cols)
template <int MODE>
__global__ __launch_bounds__(256, 2) void k_gemm(int N) {
    constexpr int K = (MODE == 1) ? 64 : 192;
    const float* __restrict__ A = (MODE == 1) ? g_xa : g_h1;
    const float* __restrict__ W = (MODE == 1) ? g_W1 : g_W2;

    __shared__ float As[16][128];
    __shared__ float Ws[16][128];
    const int rowBase = blockIdx.x * 128;
    const int colBase = blockIdx.y * 128;
    const int tid = threadIdx.x;
    const int tx = tid & 15, ty = tid >> 4;

    float acc[8][8];
#pragma unroll
    for (int i = 0; i < 8; i++)
#pragma unroll
        for (int j = 0; j < 8; j++) acc[i][j] = 0.f;

    for (int k0 = 0; k0 < K; k0 += 16) {
#pragma unroll
        for (int i = 0; i < 2; i++) {
            int f = tid * 2 + i;
            int r = f >> 2, kq = f & 3;
            int gr = rowBase + r;
            if (gr >= N) gr = N - 1;
            float4 av = *(const float4*)(A + (size_t)gr * K + k0 + kq * 4);
            As[kq * 4 + 0][r] = av.x;
            As[kq * 4 + 1][r] = av.y;
            As[kq * 4 + 2][r] = av.z;
            As[kq * 4 + 3][r] = av.w;
            int kk = f >> 5, cq = f & 31;
            float4 wv = *(const float4*)(W + (size_t)(k0 + kk) * 384 + colBase + cq * 4);
            *(float4*)&Ws[kk][cq * 4] = wv;
        }
        __syncthreads();
#pragma unroll
        for (int k = 0; k < 16; k++) {
            float a[8], b[8];
            *(float4*)&a[0] = *(float4*)&As[k][ty * 8];
            *(float4*)&a[4] = *(float4*)&As[k][ty * 8 + 4];
            *(float4*)&b[0] = *(float4*)&Ws[k][tx * 8];
            *(float4*)&b[4] = *(float4*)&Ws[k][tx * 8 + 4];
#pragma unroll
            for (int i = 0; i < 8; i++)
#pragma unroll
                for (int j = 0; j < 8; j++) acc[i][j] += a[i] * b[j];
        }
        __syncthreads();
    }

#pragma unroll
    for (int i = 0; i < 8; i++) {
        int n = rowBase + ty * 8 + i;
        if (n >= N) continue;
#pragma unroll
        for (int jq = 0; jq < 2; jq++) {
            int m = colBase + tx * 8 + jq * 4;
            float4 v = make_float4(acc[i][jq * 4], acc[i][jq * 4 + 1],
                                   acc[i][jq * 4 + 2], acc[i][jq * 4 + 3]);
            if (MODE == 1) {
                *(float4*)(g_t1 + (size_t)n * 384 + m) = v;
            } else {
                if (m < 128)       *(float4*)(g_t2lin + (size_t)n * 256 + m) = v;
                else if (m < 256)  *(float4*)(g_m2 + (size_t)n * 128 + (m - 128)) = v;
                else if (m < 320)  *(float4*)(g_t2lin + (size_t)n * 256 + 128 + (m - 256)) = v;
                else               *(float4*)(g_t2lin + (size_t)n * 256 + 192 + (m - 320)) = v;
            }
        }
    }
}

// ---------------- epilogues (relu/mul/bn) ----------------
__global__ void k_ep1(const float* __restrict__ fc11_b, const float* __restrict__ conv11_b,
                      const float* __restrict__ fc12_b, const float* __restrict__ fc13_b,
                      const float* __restrict__ gg, const float* __restrict__ bb,
                      const float* __restrict__ mm, const float* __restrict__ vv, int N) {
    int n = blockIdx.x;
    int ch = threadIdx.x;  // 192
    if (n >= N) return;
    const float* t = g_t1 + (size_t)n * 384;
    float val;
    if (ch < 128) {
        val = fmaxf(t[ch] + fc11_b[ch], 0.f) + fmaxf(t[128 + ch] + conv11_b[ch], 0.f);
    } else {
        int j = ch - 128;
        val = fmaxf(t[256 + j] + fc12_b[j], 0.f) * fmaxf(t[320 + j] + fc13_b[j], 0.f);
    }
    g_h1[(size_t)n * 192 + ch] = gg[ch] * (val - mm[ch]) * rsqrtf(vv[ch] + 1e-5f) + bb[ch];
}

// agg2[v] = sum_{u->v} m2[u]  (128 dims; warp per node, float4 per lane)
__global__ void k_agg2(int N) {
    int w = (blockIdx.x * blockDim.x + threadIdx.x) >> 5;
    int lane = threadIdx.x & 31;
    if (w >= N) return;
    int e0 = g_rowptr[w], e1 = g_rowptr[w + 1];
    float4 acc = make_float4(0.f, 0.f, 0.f, 0.f);
    for (int e = e0; e < e1; e++) {
        int s = g_col[e];
        float4 v = *(const float4*)(g_m2 + (size_t)s * 128 + lane * 4);
        acc.x += v.x; acc.y += v.y; acc.z += v.z; acc.w += v.w;
    }
    *(float4*)(g_agg2 + (size_t)w * 128 + lane * 4) = acc;
}

__global__ void k_ep2(const float* __restrict__ fc21_b, const float* __restrict__ conv21_b,
                      const float* __restrict__ fc22_b, const float* __restrict__ fc23_b,
                      const float* __restrict__ gg, const float* __restrict__ bb,
                      const float* __restrict__ mm, const float* __restrict__ vv, int N) {
    int n = blockIdx.x;
    int ch = threadIdx.x;  // 192
    if (n >= N) return;
    const float* t = g_t2lin + (size_t)n * 256;
    float val;
    if (ch < 128) {
        val = fmaxf(t[ch] + fc21_b[ch], 0.f) +
              fmaxf(g_agg2[(size_t)n * 128 + ch] + conv21_b[ch], 0.f);
    } else {
        int j = ch - 128;
        val = fmaxf(t[128 + j] + fc22_b[j], 0.f) * fmaxf(t[192 + j] + fc23_b[j], 0.f);
    }
    g_h2[(size_t)n * 192 + ch] = gg[ch] * (val - mm[ch]) * rsqrtf(vv[ch] + 1e-5f) + bb[ch];
}

// ---------------- pooling (batch is sorted) ----------------
__device__ __forceinline__ int lb_batch(const void* batch, int n, long long val) {
    int lo = 0, hi = n;
    while (lo < hi) {
        int mid = (lo + hi) >> 1;
        long long b = g_is64 ? ((const long long*)batch)[mid]
                             : (long long)((const int*)batch)[mid];
        if (b < val) lo = mid + 1; else hi = mid;
    }
    return lo;
}

__global__ void k_pool(const void* batch, int N) {
    int g = blockIdx.x;
    __shared__ int slo, shi;
    if (threadIdx.x == 0) {
        slo = lb_batch(batch, N, (long long)g);
        shi = lb_batch(batch, N, (long long)g + 1);
    }
    __syncthreads();
    int lo = slo, hi = shi;
    int ch = threadIdx.x;  // 192
    float sum = 0.f, mx = -3.402823466e38f;
    for (int n = lo; n < hi; n++) {
        float v = g_h2[(size_t)n * 192 + ch];
        sum += v;
        mx = fmaxf(mx, v);
    }
    int cnt = hi - lo;
    g_pool[g * 384 + ch] = sum / fmaxf((float)cnt, 1.f);
    g_pool[g * 384 + 192 + ch] = (cnt > 0) ? mx : 0.f;
}

// ---------------- head: logits + log_softmax ----------------
__global__ void k_head(const float* __restrict__ w, const float* __restrict__ b,
                       float* __restrict__ out, int G) {
    int t = blockIdx.x * blockDim.x + threadIdx.x;
    int warp = t >> 5, lane = t & 31;
    if (warp >= G) return;
    float lg[6] = {0.f, 0.f, 0.f, 0.f, 0.f, 0.f};
    for (int k = lane; k < 384; k += 32) {
        float gv = g_pool[warp * 384 + k];
#pragma unroll
        for (int j = 0; j < 6; j++) lg[j] += gv * w[k * 6 + j];
    }
#pragma unroll
    for (int off = 16; off; off >>= 1)
#pragma unroll
        for (int j = 0; j < 6; j++) lg[j] += __shfl_xor_sync(0xffffffffu, lg[j], off);
    if (lane == 0) {
        float v[6];
        float mx = -3.402823466e38f;
#pragma unroll
        for (int j = 0; j < 6; j++) { v[j] = lg[j] + b[j]; mx = fmaxf(mx, v[j]); }
        float s = 0.f;
#pragma unroll
        for (int j = 0; j < 6; j++) s += expf(v[j] - mx);
        float lse = mx + logf(s);
#pragma unroll
        for (int j = 0; j < 6; j++) out[warp * 6 + j] = v[j] - lse;
    }
}

// ---------------- launch ----------------
extern "C" void kernel_launch(void* const* d_in, const int* in_sizes, int n_in,
                              void* d_out, int out_size) {
    // num_graphs may or may not occupy an input slot
    int base = (n_in >= 30) ? 4 : 3;
    const float* x        = (const float*)d_in[0];
    const void*  ei       = d_in[1];
    const void*  batch    = d_in[2];
    const float* fc11_w   = (const float*)d_in[base + 0];
    const float* fc11_b   = (const float*)d_in[base + 1];
    const float* conv11_w = (const float*)d_in[base + 2];
    const float* conv11_b = (const float*)d_in[base + 3];
    const float* fc12_w   = (const float*)d_in[base + 4];
    const float* fc12_b   = (const float*)d_in[base + 5];
    const float* fc13_w   = (const float*)d_in[base + 6];
    const float* fc13_b   = (const float*)d_in[base + 7];
    const float* bn1_g    = (const float*)d_in[base + 8];
    const float* bn1_b    = (const float*)d_in[base + 9];
    const float* bn1_m    = (const float*)d_in[base + 10];
    const float* bn1_v    = (const float*)d_in[base + 11];
    const float* fc21_w   = (const float*)d_in[base + 12];
    const float* fc21_b   = (const float*)d_in[base + 13];
    const float* conv21_w = (const float*)d_in[base + 14];
    const float* conv21_b = (const float*)d_in[base + 15];
    const float* fc22_w   = (const float*)d_in[base + 16];
    const float* fc22_b   = (const float*)d_in[base + 17];
    const float* fc23_w   = (const float*)d_in[base + 18];
    const float* fc23_b   = (const float*)d_in[base + 19];
    const float* bn2_g    = (const float*)d_in[base + 20];
    const float* bn2_b    = (const float*)d_in[base + 21];
    const float* bn2_m    = (const float*)d_in[base + 22];
    const float* bn2_v    = (const float*)d_in[base + 23];
    const float* fc2_w    = (const float*)d_in[base + 24];
    const float* fc2_b    = (const float*)d_in[base + 25];

    int N = in_sizes[0] / 32;
    int E = in_sizes[1] / 2;
    int G = out_size / 6;
    float* out = (float*)d_out;

    // CSR build
    k_detect<<<1, 32>>>((const unsigned int*)ei);
    k_zero_deg<<<(N + 255) / 256, 256>>>(N);
    k_hist<<<(E + 255) / 256, 256>>>(ei, E);
    k_scan<<<1, 1024>>>(N);
    k_fill<<<(E + 255) / 256, 256>>>(ei, E);

    // block 1: aggregate raw features, pack, GEMM, epilogue
    k_agg1<<<(N * 32 + 255) / 256, 256>>>(x, N);
    k_pack_xa<<<(N * 64 + 255) / 256, 256>>>(x, N);
    k_pack_w1<<<(64 * 384 + 255) / 256, 256>>>(fc11_w, conv11_w, fc12_w, fc13_w);
    k_pack_w2<<<(192 * 384 + 255) / 256, 256>>>(fc21_w, conv21_w, fc22_w, fc23_w);
    dim3 gg((N + 127) / 128, 3);
    k_gemm<1><<<gg, 256>>>(N);
    k_ep1<<<N, 192>>>(fc11_b, conv11_b, fc12_b, fc13_b, bn1_g, bn1_b, bn1_m, bn1_v, N);

    // block 2: GEMM (lin + messages), aggregate messages, epilogue
    k_gemm<2><<<gg, 256>>>(N);
    k_agg2<<<(N * 32 + 255) / 256, 256>>>(N);
    k_ep2<<<N, 192>>>(fc21_b, conv21_b, fc22_b, fc23_b, bn2_g, bn2_b, bn2_m, bn2_v, N);

    // pooling + head
    k_pool<<<G, 192>>>(batch, N);
    k_head<<<(G * 32 + 255) / 256, 256>>>(fc2_w, fc2_b, out, G);
}

// round 2
// speedup vs baseline: 1.5087x; 1.5087x over previous
#include <cuda_runtime.h>
#include <stdint.h>

// ---------------- problem constants ----------------
#define MAXN 50000
#define MAXE 1600000
#define MAXG 1024

// ---------------- device scratch ----------------
__device__ int   g_is64;
__device__ int   g_deg[MAXN];
__device__ int   g_rowptr[MAXN + 1];
__device__ int   g_cursor[MAXN];
__device__ int   g_bsum[64];
__device__ int   g_boff[64];
__device__ int   g_col[MAXE];
__device__ float g_agg1[MAXN * 32];
__device__ float g_xa[MAXN * 64];
__device__ float g_W1[64 * 384];
__device__ float g_W2[192 * 384];
__device__ float g_t1[(size_t)MAXN * 384];
__device__ float g_h1[(size_t)MAXN * 192];
__device__ float g_t2lin[(size_t)MAXN * 256];
__device__ float g_m2[(size_t)MAXN * 128];
__device__ float g_agg2[(size_t)MAXN * 128];
__device__ float g_h2[(size_t)MAXN * 192];
__device__ float g_pool[MAXG * 384];

// ---------------- index decode (int64 vs int32, runtime-detected) ----------
__device__ __forceinline__ int ld_index(const void* p, long long i) {
    if (g_is64) return (int)((const long long*)p)[i];
    return ((const int*)p)[i];
}

__global__ void k_detect(const unsigned int* ei) {
    if (blockIdx.x == 0 && threadIdx.x == 0) {
        int ok = 1;
        for (int i = 1; i < 64; i += 2)
            if (ei[i] != 0u) ok = 0;
        g_is64 = ok;
    }
}

__global__ void k_zero_deg(int n) {
    int i = blockIdx.x * blockDim.x + threadIdx.x;
    if (i < n) g_deg[i] = 0;
}

__global__ void k_hist(const void* ei, int E) {
    int i = blockIdx.x * blockDim.x + threadIdx.x;
    if (i < E) {
        int d = ld_index(ei, (long long)E + i);   // dst row
        atomicAdd(&g_deg[d], 1);
    }
}

// ---------------- multi-block scan ----------------
// scan_a: each 1024-thread block does a local exclusive scan via shuffles,
// writes local-exclusive into rowptr and its block total into g_bsum.
__global__ void k_scan_a(int n) {
    __shared__ int wsum[32];
    int tid = threadIdx.x;
    int i = blockIdx.x * 1024 + tid;
    int lane = tid & 31, warp = tid >> 5;
    int v = (i < n) ? g_deg[i] : 0;
    // warp inclusive scan
    int s = v;
#pragma unroll
    for (int off = 1; off < 32; off <<= 1) {
        int t = __shfl_up_sync(0xffffffffu, s, off);
        if (lane >= off) s += t;
    }
    if (lane == 31) wsum[warp] = s;
    __syncthreads();
    if (warp == 0) {
        int w = wsum[lane];
        int ws = w;
#pragma unroll
        for (int off = 1; off < 32; off <<= 1) {
            int t = __shfl_up_sync(0xffffffffu, ws, off);
            if (lane >= off) ws += t;
        }
        wsum[lane] = ws - w;  // exclusive warp offsets
        if (lane == 31) g_bsum[blockIdx.x] = ws;  // block total
    }
    __syncthreads();
    if (i < n) g_rowptr[i] = (s - v) + wsum[warp];
}

// scan_b: single small block: exclusive scan of block sums
__global__ void k_scan_b(int nb) {
    int tid = threadIdx.x;  // 64 threads
    int v = (tid < nb) ? g_bsum[tid] : 0;
    int s = v;
    int lane = tid & 31, warp = tid >> 5;
    __shared__ int wsum[2];
#pragma unroll
    for (int off = 1; off < 32; off <<= 1) {
        int t = __shfl_up_sync(0xffffffffu, s, off);
        if (lane >= off) s += t;
    }
    if (lane == 31) wsum[warp] = s;
    __syncthreads();
    int add = (warp == 1) ? wsum[0] : 0;
    if (tid < nb) g_boff[tid] = (s - v) + add;
}

// scan_c: add block offsets, init cursor, write final rowptr[n]
__global__ void k_scan_c(int n, int E) {
    int i = blockIdx.x * blockDim.x + threadIdx.x;
    if (i < n) {
        int r = g_rowptr[i] + g_boff[i >> 10];
        g_rowptr[i] = r;
        g_cursor[i] = r;
    }
    if (i == 0) g_rowptr[n] = E;
}

__global__ void k_fill(const void* ei, int E) {
    int i = blockIdx.x * blockDim.x + threadIdx.x;
    if (i < E) {
        int s = ld_index(ei, i);
        int d = ld_index(ei, (long long)E + i);
        int p = atomicAdd(&g_cursor[d], 1);
        g_col[p] = s;
    }
}

// agg1[v] = sum_{u->v} x[u]   (32 dims; warp per node, lane = feature)
__global__ void k_agg1(const float* __restrict__ x, int N) {
    int w = (blockIdx.x * blockDim.x + threadIdx.x) >> 5;
    int lane = threadIdx.x & 31;
    if (w >= N) return;
    int e0 = g_rowptr[w], e1 = g_rowptr[w + 1];
    float acc = 0.f;
    for (int e = e0; e < e1; e++) {
        int s = g_col[e];
        acc += __ldg(&x[s * 32 + lane]);
    }
    g_agg1[w * 32 + lane] = acc;
}

// xa = [x | agg1]  (N x 64)
__global__ void k_pack_xa(const float* __restrict__ x, int N) {
    int i = blockIdx.x * blockDim.x + threadIdx.x;
    if (i >= N * 64) return;
    int n = i >> 6, k = i & 63;
    g_xa[i] = (k < 32) ? x[n * 32 + k] : g_agg1[n * 32 + (k - 32)];
}

// W1 pack [64 x 384]
__global__ void k_pack_w1(const float* fc11, const float* conv11,
                          const float* fc12, const float* fc13) {
    int i = blockIdx.x * blockDim.x + threadIdx.x;
    if (i >= 64 * 384) return;
    int k = i / 384, m = i % 384;
    float v = 0.f;
    if (k < 32) {
        if (m < 128)                 v = fc11[k * 128 + m];
        else if (m >= 256 && m < 320) v = fc12[k * 64 + (m - 256)];
        else if (m >= 320)            v = fc13[k * 64 + (m - 320)];
    } else {
        if (m >= 128 && m < 256)      v = conv11[(k - 32) * 128 + (m - 128)];
    }
    g_W1[i] = v;
}

// W2 pack [192 x 384]
__global__ void k_pack_w2(const float* fc21, const float* conv21,
                          const float* fc22, const float* fc23) {
    int i = blockIdx.x * blockDim.x + threadIdx.x;
    if (i >= 192 * 384) return;
    int k = i / 384, m = i % 384;
    float v;
    if (m < 128)      v = fc21[k * 128 + m];
    else if (m < 256) v = conv21[k * 128 + (m - 128)];
    else if (m < 320) v = fc22[k * 64 + (m - 256)];
    else              v = fc23[k * 64 + (m - 320)];
    g_W2[i] = v;
}

// ---------------- TF32 tensor-core GEMM ----------------
__device__ __forceinline__ uint32_t f2tf32(float f) {
    uint32_t u;
    asm("cvt.rna.tf32.f32 %0, %1;" : "=r"(u) : "f"(f));
    return u;
}

__device__ __forceinline__ void mma_tf32(float& d0, float& d1, float& d2, float& d3,
                                         uint32_t a0, uint32_t a1, uint32_t a2, uint32_t a3,
                                         uint32_t b0, uint32_t b1) {
    asm volatile("mma.sync.aligned.m16n8k8.row.col.f32.tf32.tf32.f32 "
                 "{%0,%1,%2,%3},{%4,%5,%6,%7},{%8,%9},{%0,%1,%2,%3};\n"
                 : "+f"(d0), "+f"(d1), "+f"(d2), "+f"(d3)
                 : "r"(a0), "r"(a1), "r"(a2), "r"(a3), "r"(b0), "r"(b1));
}

template <int MODE>
__device__ __forceinline__ void store_c(int n, int m, float v0, float v1, int N) {
    if (n >= N) return;
    if (MODE == 1) {
        *(float2*)(g_t1 + (size_t)n * 384 + m) = make_float2(v0, v1);
    } else {
        if (m < 128)       *(float2*)(g_t2lin + (size_t)n * 256 + m) = make_float2(v0, v1);
        else if (m < 256)  *(float2*)(g_m2 + (size_t)n * 128 + (m - 128)) = make_float2(v0, v1);
        else if (m < 320)  *(float2*)(g_t2lin + (size_t)n * 256 + 128 + (m - 256)) = make_float2(v0, v1);
        else               *(float2*)(g_t2lin + (size_t)n * 256 + 192 + (m - 320)) = make_float2(v0, v1);
    }
}

// C[N,384] = A[N,K] @ W[K,384], block tile 128x128, warp tile 64x32.
template <int MODE>
__global__ __launch_bounds__(256, 2) void k_gemm_tc(int N) {
    constexpr int K = (MODE == 1) ? 64 : 192;
    const float* __restrict__ A = (MODE == 1) ? g_xa : g_h1;
    const float* __restrict__ W = (MODE == 1) ? g_W1 : g_W2;

    __shared__ uint32_t As[128 * 12];   // [m][k] stride 12 (conflict-free frag reads)
    __shared__ uint32_t Ws[128 * 12];   // [n][k] stride 12

    const int rowBase = blockIdx.x * 128;
    const int colBase = blockIdx.y * 128;
    const int tid = threadIdx.x;
    const int warp = tid >> 5, lane = tid & 31;
    const int wm = warp >> 2, wn = warp & 3;   // 2 x 4 warp grid
    const int gq = lane >> 2, tq = lane & 3;   // groupID, threadID_in_group

    float acc[4][4][4];
#pragma unroll
    for (int i = 0; i < 4; i++)
#pragma unroll
        for (int j = 0; j < 4; j++)
#pragma unroll
            for (int c = 0; c < 4; c++) acc[i][j][c] = 0.f;

    const int ar = tid >> 1, ah = tid & 1;     // A staging: row, half
    const int wc = tid & 127, wkp = tid >> 7;  // W staging: col, k-quad

    for (int k0 = 0; k0 < K; k0 += 8) {
        // stage A (rows clamp for tail block)
        int gr = rowBase + ar;
        if (gr >= N) gr = N - 1;
        float4 av = *(const float4*)(A + (size_t)gr * K + k0 + ah * 4);
        uint32_t* ad = &As[ar * 12 + ah * 4];
        ad[0] = f2tf32(av.x); ad[1] = f2tf32(av.y);
        ad[2] = f2tf32(av.z); ad[3] = f2tf32(av.w);
        // stage W transposed
#pragma unroll
        for (int i = 0; i < 4; i++) {
            float wv = W[(size_t)(k0 + wkp * 4 + i) * 384 + colBase + wc];
            Ws[wc * 12 + wkp * 4 + i] = f2tf32(wv);
        }
        __syncthreads();

        uint32_t af[4][4], bf[4][2];
#pragma unroll
        for (int i = 0; i < 4; i++) {
            int m0 = wm * 64 + i * 16;
            af[i][0] = As[(m0 + gq) * 12 + tq];
            af[i][1] = As[(m0 + gq + 8) * 12 + tq];
            af[i][2] = As[(m0 + gq) * 12 + tq + 4];
            af[i][3] = As[(m0 + gq + 8) * 12 + tq + 4];
        }
#pragma unroll
        for (int j = 0; j < 4; j++) {
            int n0 = wn * 32 + j * 8;
            bf[j][0] = Ws[(n0 + gq) * 12 + tq];
            bf[j][1] = Ws[(n0 + gq) * 12 + tq + 4];
        }
#pragma unroll
        for (int i = 0; i < 4; i++)
#pragma unroll
            for (int j = 0; j < 4; j++)
                mma_tf32(acc[i][j][0], acc[i][j][1], acc[i][j][2], acc[i][j][3],
                         af[i][0], af[i][1], af[i][2], af[i][3],
                         bf[j][0], bf[j][1]);
        __syncthreads();
    }

#pragma unroll
    for (int i = 0; i < 4; i++) {
#pragma unroll
        for (int j = 0; j < 4; j++) {
            int col = colBase + wn * 32 + j * 8 + tq * 2;
            int r0 = rowBase + wm * 64 + i * 16 + gq;
            store_c<MODE>(r0,     col, acc[i][j][0], acc[i][j][1], N);
            store_c<MODE>(r0 + 8, col, acc[i][j][2], acc[i][j][3], N);
        }
    }
}

// ---------------- epilogues (relu/mul/bn) ----------------
__global__ void k_ep1(const float* __restrict__ fc11_b, const float* __restrict__ conv11_b,
                      const float* __restrict__ fc12_b, const float* __restrict__ fc13_b,
                      const float* __restrict__ gg, const float* __restrict__ bb,
                      const float* __restrict__ mm, const float* __restrict__ vv, int N) {
    int n = blockIdx.x;
    int ch = threadIdx.x;  // 192
    if (n >= N) return;
    const float* t = g_t1 + (size_t)n * 384;
    float val;
    if (ch < 128) {
        val = fmaxf(t[ch] + fc11_b[ch], 0.f) + fmaxf(t[128 + ch] + conv11_b[ch], 0.f);
    } else {
        int j = ch - 128;
        val = fmaxf(t[256 + j] + fc12_b[j], 0.f) * fmaxf(t[320 + j] + fc13_b[j], 0.f);
    }
    g_h1[(size_t)n * 192 + ch] = gg[ch] * (val - mm[ch]) * rsqrtf(vv[ch] + 1e-5f) + bb[ch];
}

// agg2[v] = sum_{u->v} m2[u]  (128 dims; warp per node, float4 per lane)
__global__ void k_agg2(int N) {
    int w = (blockIdx.x * blockDim.x + threadIdx.x) >> 5;
    int lane = threadIdx.x & 31;
    if (w >= N) return;
    int e0 = g_rowptr[w], e1 = g_rowptr[w + 1];
    float4 acc = make_float4(0.f, 0.f, 0.f, 0.f);
    for (int e = e0; e < e1; e++) {
        int s = g_col[e];
        float4 v = *(const float4*)(g_m2 + (size_t)s * 128 + lane * 4);
        acc.x += v.x; acc.y += v.y; acc.z += v.z; acc.w += v.w;
    }
    *(float4*)(g_agg2 + (size_t)w * 128 + lane * 4) = acc;
}

__global__ void k_ep2(const float* __restrict__ fc21_b, const float* __restrict__ conv21_b,
                      const float* __restrict__ fc22_b, const float* __restrict__ fc23_b,
                      const float* __restrict__ gg, const float* __restrict__ bb,
                      const float* __restrict__ mm, const float* __restrict__ vv, int N) {
    int n = blockIdx.x;
    int ch = threadIdx.x;  // 192
    if (n >= N) return;
    const float* t = g_t2lin + (size_t)n * 256;
    float val;
    if (ch < 128) {
        val = fmaxf(t[ch] + fc21_b[ch], 0.f) +
              fmaxf(g_agg2[(size_t)n * 128 + ch] + conv21_b[ch], 0.f);
    } else {
        int j = ch - 128;
        val = fmaxf(t[128 + j] + fc22_b[j], 0.f) * fmaxf(t[192 + j] + fc23_b[j], 0.f);
    }
    g_h2[(size_t)n * 192 + ch] = gg[ch] * (val - mm[ch]) * rsqrtf(vv[ch] + 1e-5f) + bb[ch];
}

// ---------------- pooling (batch is sorted) ----------------
__device__ __forceinline__ int lb_batch(const void* batch, int n, long long val) {
    int lo = 0, hi = n;
    while (lo < hi) {
        int mid = (lo + hi) >> 1;
        long long b = g_is64 ? ((const long long*)batch)[mid]
                             : (long long)((const int*)batch)[mid];
        if (b < val) lo = mid + 1; else hi = mid;
    }
    return lo;
}

__global__ void k_pool(const void* batch, int N) {
    int g = blockIdx.x;
    __shared__ int slo, shi;
    if (threadIdx.x == 0) {
        slo = lb_batch(batch, N, (long long)g);
        shi = lb_batch(batch, N, (long long)g + 1);
    }
    __syncthreads();
    int lo = slo, hi = shi;
    int ch = threadIdx.x;  // 192
    float sum = 0.f, mx = -3.402823466e38f;
    for (int n = lo; n < hi; n++) {
        float v = g_h2[(size_t)n * 192 + ch];
        sum += v;
        mx = fmaxf(mx, v);
    }
    int cnt = hi - lo;
    g_pool[g * 384 + ch] = sum / fmaxf((float)cnt, 1.f);
    g_pool[g * 384 + 192 + ch] = (cnt > 0) ? mx : 0.f;
}

// ---------------- head: logits + log_softmax ----------------
__global__ void k_head(const float* __restrict__ w, const float* __restrict__ b,
                       float* __restrict__ out, int G) {
    int t = blockIdx.x * blockDim.x + threadIdx.x;
    int warp = t >> 5, lane = t & 31;
    if (warp >= G) return;
    float lg[6] = {0.f, 0.f, 0.f, 0.f, 0.f, 0.f};
    for (int k = lane; k < 384; k += 32) {
        float gv = g_pool[warp * 384 + k];
#pragma unroll
        for (int j = 0; j < 6; j++) lg[j] += gv * w[k * 6 + j];
    }
#pragma unroll
    for (int off = 16; off; off >>= 1)
#pragma unroll
        for (int j = 0; j < 6; j++) lg[j] += __shfl_xor_sync(0xffffffffu, lg[j], off);
    if (lane == 0) {
        float v[6];
        float mx = -3.402823466e38f;
#pragma unroll
        for (int j = 0; j < 6; j++) { v[j] = lg[j] + b[j]; mx = fmaxf(mx, v[j]); }
        float s = 0.f;
#pragma unroll
        for (int j = 0; j < 6; j++) s += expf(v[j] - mx);
        float lse = mx + logf(s);
#pragma unroll
        for (int j = 0; j < 6; j++) out[warp * 6 + j] = v[j] - lse;
    }
}

// ---------------- launch ----------------
extern "C" void kernel_launch(void* const* d_in, const int* in_sizes, int n_in,
                              void* d_out, int out_size) {
    int base = (n_in >= 30) ? 4 : 3;
    const float* x        = (const float*)d_in[0];
    const void*  ei       = d_in[1];
    const void*  batch    = d_in[2];
    const float* fc11_w   = (const float*)d_in[base + 0];
    const float* fc11_b   = (const float*)d_in[base + 1];
    const float* conv11_w = (const float*)d_in[base + 2];
    const float* conv11_b = (const float*)d_in[base + 3];
    const float* fc12_w   = (const float*)d_in[base + 4];
    const float* fc12_b   = (const float*)d_in[base + 5];
    const float* fc13_w   = (const float*)d_in[base + 6];
    const float* fc13_b   = (const float*)d_in[base + 7];
    const float* bn1_g    = (const float*)d_in[base + 8];
    const float* bn1_b    = (const float*)d_in[base + 9];
    const float* bn1_m    = (const float*)d_in[base + 10];
    const float* bn1_v    = (const float*)d_in[base + 11];
    const float* fc21_w   = (const float*)d_in[base + 12];
    const float* fc21_b   = (const float*)d_in[base + 13];
    const float* conv21_w = (const float*)d_in[base + 14];
    const float* conv21_b = (const float*)d_in[base + 15];
    const float* fc22_w   = (const float*)d_in[base + 16];
    const float* fc22_b   = (const float*)d_in[base + 17];
    const float* fc23_w   = (const float*)d_in[base + 18];
    const float* fc23_b   = (const float*)d_in[base + 19];
    const float* bn2_g    = (const float*)d_in[base + 20];
    const float* bn2_b    = (const float*)d_in[base + 21];
    const float* bn2_m    = (const float*)d_in[base + 22];
    const float* bn2_v    = (const float*)d_in[base + 23];
    const float* fc2_w    = (const float*)d_in[base + 24];
    const float* fc2_b    = (const float*)d_in[base + 25];

    int N = in_sizes[0] / 32;
    int E = in_sizes[1] / 2;
    int G = out_size / 6;
    float* out = (float*)d_out;

    // CSR build
    k_detect<<<1, 32>>>((const unsigned int*)ei);
    k_zero_deg<<<(N + 255) / 256, 256>>>(N);
    k_hist<<<(E + 255) / 256, 256>>>(ei, E);
    int nb = (N + 1023) / 1024;
    k_scan_a<<<nb, 1024>>>(N);
    k_scan_b<<<1, 64>>>(nb);
    k_scan_c<<<(N + 255) / 256, 256>>>(N, E);
    k_fill<<<(E + 255) / 256, 256>>>(ei, E);

    // block 1
    k_agg1<<<(N * 32 + 255) / 256, 256>>>(x, N);
    k_pack_xa<<<(N * 64 + 255) / 256, 256>>>(x, N);
    k_pack_w1<<<(64 * 384 + 255) / 256, 256>>>(fc11_w, conv11_w, fc12_w, fc13_w);
    k_pack_w2<<<(192 * 384 + 255) / 256, 256>>>(fc21_w, conv21_w, fc22_w, fc23_w);
    dim3 gg((N + 127) / 128, 3);
    k_gemm_tc<1><<<gg, 256>>>(N);
    k_ep1<<<N, 192>>>(fc11_b, conv11_b, fc12_b, fc13_b, bn1_g, bn1_b, bn1_m, bn1_v, N);

    // block 2
    k_gemm_tc<2><<<gg, 256>>>(N);
    k_agg2<<<(N * 32 + 255) / 256, 256>>>(N);
    k_ep2<<<N, 192>>>(fc21_b, conv21_b, fc22_b, fc23_b, bn2_g, bn2_b, bn2_m, bn2_v, N);

    // pooling + head
    k_pool<<<G, 192>>>(batch, N);
    k_head<<<(G * 32 + 255) / 256, 256>>>(fc2_w, fc2_b, out, G);
}

// round 3
// speedup vs baseline: 1.6269x; 1.0783x over previous
#include <cuda_runtime.h>
#include <stdint.h>

// ---------------- problem constants ----------------
#define MAXN 50000
#define MAXE 1600000
#define MAXG 1024

// ---------------- device scratch ----------------
__device__ int   g_is64;
__device__ int   g_deg[MAXN];
__device__ int   g_rowptr[MAXN + 1];
__device__ int   g_cursor[MAXN];
__device__ int   g_bsum[64];
__device__ int   g_boff[64];
__device__ int   g_col[MAXE];
__device__ float g_agg1[MAXN * 32];
__device__ float g_xa[MAXN * 64];
__device__ float g_W1[64 * 384];
__device__ float g_W2[192 * 384];
__device__ float g_h1[(size_t)MAXN * 192];
__device__ float g_lin[(size_t)MAXN * 128];   // relu(fc21) part of block 2
__device__ float g_cprod[(size_t)MAXN * 64];  // relu(fc22)*relu(fc23) part
__device__ float g_m2[(size_t)MAXN * 128];    // raw conv21 messages
__device__ float g_agg2[(size_t)MAXN * 128];
__device__ float g_h2[(size_t)MAXN * 192];
__device__ float g_pool[MAXG * 384];

// ---------------- index decode (int64 vs int32, runtime-detected) ----------
__device__ __forceinline__ int ld_index(const void* p, long long i) {
    if (g_is64) return (int)((const long long*)p)[i];
    return ((const int*)p)[i];
}

__global__ void k_detect(const unsigned int* ei) {
    if (blockIdx.x == 0 && threadIdx.x == 0) {
        int ok = 1;
        for (int i = 1; i < 64; i += 2)
            if (ei[i] != 0u) ok = 0;
        g_is64 = ok;
    }
}

__global__ void k_zero_deg(int n) {
    int i = blockIdx.x * blockDim.x + threadIdx.x;
    if (i < n) g_deg[i] = 0;
}

__global__ void k_hist(const void* ei, int E) {
    int i = blockIdx.x * blockDim.x + threadIdx.x;
    if (i < E) {
        int d = ld_index(ei, (long long)E + i);   // dst row
        atomicAdd(&g_deg[d], 1);
    }
}

// ---------------- multi-block scan ----------------
__global__ void k_scan_a(int n) {
    __shared__ int wsum[32];
    int tid = threadIdx.x;
    int i = blockIdx.x * 1024 + tid;
    int lane = tid & 31, warp = tid >> 5;
    int v = (i < n) ? g_deg[i] : 0;
    int s = v;
#pragma unroll
    for (int off = 1; off < 32; off <<= 1) {
        int t = __shfl_up_sync(0xffffffffu, s, off);
        if (lane >= off) s += t;
    }
    if (lane == 31) wsum[warp] = s;
    __syncthreads();
    if (warp == 0) {
        int w = wsum[lane];
        int ws = w;
#pragma unroll
        for (int off = 1; off < 32; off <<= 1) {
            int t = __shfl_up_sync(0xffffffffu, ws, off);
            if (lane >= off) ws += t;
        }
        wsum[lane] = ws - w;
        if (lane == 31) g_bsum[blockIdx.x] = ws;
    }
    __syncthreads();
    if (i < n) g_rowptr[i] = (s - v) + wsum[warp];
}

__global__ void k_scan_b(int nb) {
    int tid = threadIdx.x;  // 64 threads
    int v = (tid < nb) ? g_bsum[tid] : 0;
    int s = v;
    int lane = tid & 31, warp = tid >> 5;
    __shared__ int wsum[2];
#pragma unroll
    for (int off = 1; off < 32; off <<= 1) {
        int t = __shfl_up_sync(0xffffffffu, s, off);
        if (lane >= off) s += t;
    }
    if (lane == 31) wsum[warp] = s;
    __syncthreads();
    int add = (warp == 1) ? wsum[0] : 0;
    if (tid < nb) g_boff[tid] = (s - v) + add;
}

__global__ void k_scan_c(int n, int E) {
    int i = blockIdx.x * blockDim.x + threadIdx.x;
    if (i < n) {
        int r = g_rowptr[i] + g_boff[i >> 10];
        g_rowptr[i] = r;
        g_cursor[i] = r;
    }
    if (i == 0) g_rowptr[n] = E;
}

__global__ void k_fill(const void* ei, int E) {
    int i = blockIdx.x * blockDim.x + threadIdx.x;
    if (i < E) {
        int s = ld_index(ei, i);
        int d = ld_index(ei, (long long)E + i);
        int p = atomicAdd(&g_cursor[d], 1);
        g_col[p] = s;
    }
}

// agg1[v] = sum_{u->v} x[u]  (32 dims; warp per node, lane = feature, unroll 4)
__global__ void k_agg1(const float* __restrict__ x, int N) {
    int w = (blockIdx.x * blockDim.x + threadIdx.x) >> 5;
    int lane = threadIdx.x & 31;
    if (w >= N) return;
    int e0 = g_rowptr[w], e1 = g_rowptr[w + 1];
    float acc = 0.f;
    int e = e0;
    for (; e + 4 <= e1; e += 4) {
        int s0 = g_col[e], s1 = g_col[e + 1], s2 = g_col[e + 2], s3 = g_col[e + 3];
        float v0 = __ldg(&x[s0 * 32 + lane]);
        float v1 = __ldg(&x[s1 * 32 + lane]);
        float v2 = __ldg(&x[s2 * 32 + lane]);
        float v3 = __ldg(&x[s3 * 32 + lane]);
        acc += (v0 + v1) + (v2 + v3);
    }
    for (; e < e1; e++) acc += __ldg(&x[g_col[e] * 32 + lane]);
    g_agg1[w * 32 + lane] = acc;
}

// xa = [x | agg1]  (N x 64)
__global__ void k_pack_xa(const float* __restrict__ x, int N) {
    int i = blockIdx.x * blockDim.x + threadIdx.x;
    if (i >= N * 64) return;
    int n = i >> 6, k = i & 63;
    g_xa[i] = (k < 32) ? x[n * 32 + k] : g_agg1[n * 32 + (k - 32)];
}

// W1 pack [64 x 384], paired halves per 128-col slice:
// slice s<2: [fc11 cols s*64.. | conv11 cols s*64..]; slice 2: [fc12 | fc13]
// rows: fc* use k<32 (x part), conv11 uses k>=32 (agg part)
__global__ void k_pack_w1(const float* fc11, const float* conv11,
                          const float* fc12, const float* fc13) {
    int i = blockIdx.x * blockDim.x + threadIdx.x;
    if (i >= 64 * 384) return;
    int k = i / 384, m = i % 384;
    int s = m >> 7, l = m & 127, half = l >> 6, c = l & 63;
    float v = 0.f;
    if (s < 2) {
        int ch = s * 64 + c;
        if (half == 0) { if (k < 32) v = fc11[k * 128 + ch]; }
        else           { if (k >= 32) v = conv11[(k - 32) * 128 + ch]; }
    } else {
        if (k < 32) v = half ? fc13[k * 64 + c] : fc12[k * 64 + c];
    }
    g_W1[i] = v;
}

// W2 pack [192 x 384], same paired layout
__global__ void k_pack_w2(const float* fc21, const float* conv21,
                          const float* fc22, const float* fc23) {
    int i = blockIdx.x * blockDim.x + threadIdx.x;
    if (i >= 192 * 384) return;
    int k = i / 384, m = i % 384;
    int s = m >> 7, l = m & 127, half = l >> 6, c = l & 63;
    float v;
    if (s < 2) {
        int ch = s * 64 + c;
        v = half ? conv21[k * 128 + ch] : fc21[k * 128 + ch];
    } else {
        v = half ? fc23[k * 64 + c] : fc22[k * 64 + c];
    }
    g_W2[i] = v;
}

// ---------------- TF32 tensor-core GEMM w/ fused epilogue ----------------
__device__ __forceinline__ uint32_t f2tf32(float f) {
    uint32_t u;
    asm("cvt.rna.tf32.f32 %0, %1;" : "=r"(u) : "f"(f));
    return u;
}

__device__ __forceinline__ void mma_tf32(float& d0, float& d1, float& d2, float& d3,
                                         uint32_t a0, uint32_t a1, uint32_t a2, uint32_t a3,
                                         uint32_t b0, uint32_t b1) {
    asm volatile("mma.sync.aligned.m16n8k8.row.col.f32.tf32.tf32.f32 "
                 "{%0,%1,%2,%3},{%4,%5,%6,%7},{%8,%9},{%0,%1,%2,%3};\n"
                 : "+f"(d0), "+f"(d1), "+f"(d2), "+f"(d3)
                 : "r"(a0), "r"(a1), "r"(a2), "r"(a3), "r"(b0), "r"(b1));
}

// C[N,384] = A[N,K] @ W[K,384]. Block tile 128 rows x 128 cols (one slice s).
// Warp n-tiles are split: j=0,1 -> left half cols, j=2,3 -> right half cols,
// so the (lin, conv) / (fc12, fc13) column pair lives in one thread's regs.
// MODE 1: epilogue -> g_h1 (bias+relu+combine+BN fused)
// MODE 2: epilogue -> g_lin (relu'd), g_m2 (raw), g_cprod
template <int MODE>
__global__ __launch_bounds__(256, 2) void k_gemm_tc(
    int N,
    const float* __restrict__ bL1, const float* __restrict__ bR1,   // 128-ch biases (lin/conv)
    const float* __restrict__ bL2, const float* __restrict__ bR2,   // 64-ch biases (fc12/fc13 or fc22/fc23)
    const float* __restrict__ bng, const float* __restrict__ bnb,
    const float* __restrict__ bnm, const float* __restrict__ bnv) {
    constexpr int K = (MODE == 1) ? 64 : 192;
    const float* __restrict__ A = (MODE == 1) ? g_xa : g_h1;
    const float* __restrict__ W = (MODE == 1) ? g_W1 : g_W2;

    __shared__ uint32_t As[128 * 12];
    __shared__ uint32_t Ws[128 * 12];

    const int rowBase = blockIdx.x * 128;
    const int s = blockIdx.y;          // col slice 0..2
    const int colBase = s * 128;
    const int tid = threadIdx.x;
    const int warp = tid >> 5, lane = tid & 31;
    const int wm = warp >> 2, wn = warp & 3;   // 2 x 4 warp grid
    const int gq = lane >> 2, tq = lane & 3;

    float acc[4][4][4];
#pragma unroll
    for (int i = 0; i < 4; i++)
#pragma unroll
        for (int j = 0; j < 4; j++)
#pragma unroll
            for (int c = 0; c < 4; c++) acc[i][j][c] = 0.f;

    const int ar = tid >> 1, ah = tid & 1;
    const int wc = tid & 127, wkp = tid >> 7;

    for (int k0 = 0; k0 < K; k0 += 8) {
        int gr = rowBase + ar;
        if (gr >= N) gr = N - 1;
        float4 av = *(const float4*)(A + (size_t)gr * K + k0 + ah * 4);
        uint32_t* ad = &As[ar * 12 + ah * 4];
        ad[0] = f2tf32(av.x); ad[1] = f2tf32(av.y);
        ad[2] = f2tf32(av.z); ad[3] = f2tf32(av.w);
#pragma unroll
        for (int i = 0; i < 4; i++) {
            float wv = W[(size_t)(k0 + wkp * 4 + i) * 384 + colBase + wc];
            Ws[wc * 12 + wkp * 4 + i] = f2tf32(wv);
        }
        __syncthreads();

        uint32_t af[4][4], bf[4][2];
#pragma unroll
        for (int i = 0; i < 4; i++) {
            int m0 = wm * 64 + i * 16;
            af[i][0] = As[(m0 + gq) * 12 + tq];
            af[i][1] = As[(m0 + gq + 8) * 12 + tq];
            af[i][2] = As[(m0 + gq) * 12 + tq + 4];
            af[i][3] = As[(m0 + gq + 8) * 12 + tq + 4];
        }
#pragma unroll
        for (int j = 0; j < 4; j++) {
            // j=0,1 -> left half (cols wn*16 + j*8); j=2,3 -> right half (+64)
            int n0 = ((j < 2) ? 0 : 64) + wn * 16 + (j & 1) * 8;
            bf[j][0] = Ws[(n0 + gq) * 12 + tq];
            bf[j][1] = Ws[(n0 + gq) * 12 + tq + 4];
        }
#pragma unroll
        for (int i = 0; i < 4; i++)
#pragma unroll
            for (int j = 0; j < 4; j++)
                mma_tf32(acc[i][j][0], acc[i][j][1], acc[i][j][2], acc[i][j][3],
                         af[i][0], af[i][1], af[i][2], af[i][3],
                         bf[j][0], bf[j][1]);
        __syncthreads();
    }

    // fused epilogue: pairs are (acc[i][j][*], acc[i][j+2][*]) for j=0,1
#pragma unroll
    for (int i = 0; i < 4; i++) {
#pragma unroll
        for (int j = 0; j < 2; j++) {
            int l = wn * 16 + j * 8 + tq * 2;  // local col in [0,64)
#pragma unroll
            for (int p = 0; p < 2; p++) {
                int n = rowBase + wm * 64 + i * 16 + gq + p * 8;
                if (n >= N) continue;
                float o0, o1;
                if (s < 2) {
                    int ch = s * 64 + l;
                    float L0 = acc[i][j][p * 2 + 0], L1 = acc[i][j][p * 2 + 1];
                    float R0 = acc[i][j + 2][p * 2 + 0], R1 = acc[i][j + 2][p * 2 + 1];
                    if (MODE == 1) {
                        float v0 = fmaxf(L0 + __ldg(&bL1[ch]), 0.f) +
                                   fmaxf(R0 + __ldg(&bR1[ch]), 0.f);
                        float v1 = fmaxf(L1 + __ldg(&bL1[ch + 1]), 0.f) +
                                   fmaxf(R1 + __ldg(&bR1[ch + 1]), 0.f);
                        o0 = __ldg(&bng[ch]) * (v0 - __ldg(&bnm[ch])) *
                                 rsqrtf(__ldg(&bnv[ch]) + 1e-5f) + __ldg(&bnb[ch]);
                        o1 = __ldg(&bng[ch + 1]) * (v1 - __ldg(&bnm[ch + 1])) *
                                 rsqrtf(__ldg(&bnv[ch + 1]) + 1e-5f) + __ldg(&bnb[ch + 1]);
                        *(float2*)(g_h1 + (size_t)n * 192 + ch) = make_float2(o0, o1);
                    } else {
                        float r0 = fmaxf(L0 + __ldg(&bL1[ch]), 0.f);
                        float r1 = fmaxf(L1 + __ldg(&bL1[ch + 1]), 0.f);
                        *(float2*)(g_lin + (size_t)n * 128 + ch) = make_float2(r0, r1);
                        *(float2*)(g_m2 + (size_t)n * 128 + ch) = make_float2(R0, R1);
                    }
                } else {
                    float L0 = acc[i][j][p * 2 + 0], L1 = acc[i][j][p * 2 + 1];
                    float R0 = acc[i][j + 2][p * 2 + 0], R1 = acc[i][j + 2][p * 2 + 1];
                    float v0 = fmaxf(L0 + __ldg(&bL2[l]), 0.f) *
                               fmaxf(R0 + __ldg(&bR2[l]), 0.f);
                    float v1 = fmaxf(L1 + __ldg(&bL2[l + 1]), 0.f) *
                               fmaxf(R1 + __ldg(&bR2[l + 1]), 0.f);
                    if (MODE == 1) {
                        int ch = 128 + l;
                        o0 = __ldg(&bng[ch]) * (v0 - __ldg(&bnm[ch])) *
                                 rsqrtf(__ldg(&bnv[ch]) + 1e-5f) + __ldg(&bnb[ch]);
                        o1 = __ldg(&bng[ch + 1]) * (v1 - __ldg(&bnm[ch + 1])) *
                                 rsqrtf(__ldg(&bnv[ch + 1]) + 1e-5f) + __ldg(&bnb[ch + 1]);
                        *(float2*)(g_h1 + (size_t)n * 192 + ch) = make_float2(o0, o1);
                    } else {
                        *(float2*)(g_cprod + (size_t)n * 64 + l) = make_float2(v0, v1);
                    }
                }
            }
        }
    }
}

// agg2[v] = sum_{u->v} m2[u]  (128 dims; warp per node, float4/lane, unroll 4)
__global__ void k_agg2(int N) {
    int w = (blockIdx.x * blockDim.x + threadIdx.x) >> 5;
    int lane = threadIdx.x & 31;
    if (w >= N) return;
    int e0 = g_rowptr[w], e1 = g_rowptr[w + 1];
    float4 acc = make_float4(0.f, 0.f, 0.f, 0.f);
    int e = e0;
    for (; e + 4 <= e1; e += 4) {
        int s0 = g_col[e], s1 = g_col[e + 1], s2 = g_col[e + 2], s3 = g_col[e + 3];
        float4 v0 = *(const float4*)(g_m2 + (size_t)s0 * 128 + lane * 4);
        float4 v1 = *(const float4*)(g_m2 + (size_t)s1 * 128 + lane * 4);
        float4 v2 = *(const float4*)(g_m2 + (size_t)s2 * 128 + lane * 4);
        float4 v3 = *(const float4*)(g_m2 + (size_t)s3 * 128 + lane * 4);
        acc.x += (v0.x + v1.x) + (v2.x + v3.x);
        acc.y += (v0.y + v1.y) + (v2.y + v3.y);
        acc.z += (v0.z + v1.z) + (v2.z + v3.z);
        acc.w += (v0.w + v1.w) + (v2.w + v3.w);
    }
    for (; e < e1; e++) {
        int sc = g_col[e];
        float4 v = *(const float4*)(g_m2 + (size_t)sc * 128 + lane * 4);
        acc.x += v.x; acc.y += v.y; acc.z += v.z; acc.w += v.w;
    }
    *(float4*)(g_agg2 + (size_t)w * 128 + lane * 4) = acc;
}

// final block-2 epilogue
__global__ void k_ep2(const float* __restrict__ conv21_b,
                      const float* __restrict__ gg, const float* __restrict__ bb,
                      const float* __restrict__ mm, const float* __restrict__ vv, int N) {
    int n = blockIdx.x;
    int ch = threadIdx.x;  // 192
    if (n >= N) return;
    float val;
    if (ch < 128) {
        val = g_lin[(size_t)n * 128 + ch] +
              fmaxf(g_agg2[(size_t)n * 128 + ch] + conv21_b[ch], 0.f);
    } else {
        val = g_cprod[(size_t)n * 64 + (ch - 128)];
    }
    g_h2[(size_t)n * 192 + ch] = gg[ch] * (val - mm[ch]) * rsqrtf(vv[ch] + 1e-5f) + bb[ch];
}

// ---------------- pooling (batch is sorted) ----------------
__device__ __forceinline__ int lb_batch(const void* batch, int n, long long val) {
    int lo = 0, hi = n;
    while (lo < hi) {
        int mid = (lo + hi) >> 1;
        long long b = g_is64 ? ((const long long*)batch)[mid]
                             : (long long)((const int*)batch)[mid];
        if (b < val) lo = mid + 1; else hi = mid;
    }
    return lo;
}

__global__ void k_pool(const void* batch, int N) {
    int g = blockIdx.x;
    __shared__ int slo, shi;
    if (threadIdx.x == 0) {
        slo = lb_batch(batch, N, (long long)g);
        shi = lb_batch(batch, N, (long long)g + 1);
    }
    __syncthreads();
    int lo = slo, hi = shi;
    int ch = threadIdx.x;  // 192
    float sum = 0.f, mx = -3.402823466e38f;
    for (int n = lo; n < hi; n++) {
        float v = g_h2[(size_t)n * 192 + ch];
        sum += v;
        mx = fmaxf(mx, v);
    }
    int cnt = hi - lo;
    g_pool[g * 384 + ch] = sum / fmaxf((float)cnt, 1.f);
    g_pool[g * 384 + 192 + ch] = (cnt > 0) ? mx : 0.f;
}

// ---------------- head: logits + log_softmax ----------------
__global__ void k_head(const float* __restrict__ w, const float* __restrict__ b,
                       float* __restrict__ out, int G) {
    int t = blockIdx.x * blockDim.x + threadIdx.x;
    int warp = t >> 5, lane = t & 31;
    if (warp >= G) return;
    float lg[6] = {0.f, 0.f, 0.f, 0.f, 0.f, 0.f};
    for (int k = lane; k < 384; k += 32) {
        float gv = g_pool[warp * 384 + k];
#pragma unroll
        for (int j = 0; j < 6; j++) lg[j] += gv * w[k * 6 + j];
    }
#pragma unroll
    for (int off = 16; off; off >>= 1)
#pragma unroll
        for (int j = 0; j < 6; j++) lg[j] += __shfl_xor_sync(0xffffffffu, lg[j], off);
    if (lane == 0) {
        float v[6];
        float mx = -3.402823466e38f;
#pragma unroll
        for (int j = 0; j < 6; j++) { v[j] = lg[j] + b[j]; mx = fmaxf(mx, v[j]); }
        float s = 0.f;
#pragma unroll
        for (int j = 0; j < 6; j++) s += expf(v[j] - mx);
        float lse = mx + logf(s);
#pragma unroll
        for (int j = 0; j < 6; j++) out[warp * 6 + j] = v[j] - lse;
    }
}

// ---------------- launch ----------------
extern "C" void kernel_launch(void* const* d_in, const int* in_sizes, int n_in,
                              void* d_out, int out_size) {
    int base = (n_in >= 30) ? 4 : 3;
    const float* x        = (const float*)d_in[0];
    const void*  ei       = d_in[1];
    const void*  batch    = d_in[2];
    const float* fc11_w   = (const float*)d_in[base + 0];
    const float* fc11_b   = (const float*)d_in[base + 1];
    const float* conv11_w = (const float*)d_in[base + 2];
    const float* conv11_b = (const float*)d_in[base + 3];
    const float* fc12_w   = (const float*)d_in[base + 4];
    const float* fc12_b   = (const float*)d_in[base + 5];
    const float* fc13_w   = (const float*)d_in[base + 6];
    const float* fc13_b   = (const float*)d_in[base + 7];
    const float* bn1_g    = (const float*)d_in[base + 8];
    const float* bn1_b    = (const float*)d_in[base + 9];
    const float* bn1_m    = (const float*)d_in[base + 10];
    const float* bn1_v    = (const float*)d_in[base + 11];
    const float* fc21_w   = (const float*)d_in[base + 12];
    const float* fc21_b   = (const float*)d_in[base + 13];
    const float* conv21_w = (const float*)d_in[base + 14];
    const float* conv21_b = (const float*)d_in[base + 15];
    const float* fc22_w   = (const float*)d_in[base + 16];
    const float* fc22_b   = (const float*)d_in[base + 17];
    const float* fc23_w   = (const float*)d_in[base + 18];
    const float* fc23_b   = (const float*)d_in[base + 19];
    const float* bn2_g    = (const float*)d_in[base + 20];
    const float* bn2_b    = (const float*)d_in[base + 21];
    const float* bn2_m    = (const float*)d_in[base + 22];
    const float* bn2_v    = (const float*)d_in[base + 23];
    const float* fc2_w    = (const float*)d_in[base + 24];
    const float* fc2_b    = (const float*)d_in[base + 25];

    int N = in_sizes[0] / 32;
    int E = in_sizes[1] / 2;
    int G = out_size / 6;
    float* out = (float*)d_out;

    // CSR build
    k_detect<<<1, 32>>>((const unsigned int*)ei);
    k_zero_deg<<<(N + 255) / 256, 256>>>(N);
    k_hist<<<(E + 255) / 256, 256>>>(ei, E);
    int nb = (N + 1023) / 1024;
    k_scan_a<<<nb, 1024>>>(N);
    k_scan_b<<<1, 64>>>(nb);
    k_scan_c<<<(N + 255) / 256, 256>>>(N, E);
    k_fill<<<(E + 255) / 256, 256>>>(ei, E);

    // block 1: aggregate raw feats, pack, fused GEMM -> h1
    k_agg1<<<(N * 32 + 255) / 256, 256>>>(x, N);
    k_pack_xa<<<(N * 64 + 255) / 256, 256>>>(x, N);
    k_pack_w1<<<(64 * 384 + 255) / 256, 256>>>(fc11_w, conv11_w, fc12_w, fc13_w);
    k_pack_w2<<<(192 * 384 + 255) / 256, 256>>>(fc21_w, conv21_w, fc22_w, fc23_w);
    dim3 gg((N + 127) / 128, 3);
    k_gemm_tc<1><<<gg, 256>>>(N, fc11_b, conv11_b, fc12_b, fc13_b,
                              bn1_g, bn1_b, bn1_m, bn1_v);

    // block 2: fused GEMM -> lin/m2/cprod, aggregate, final epilogue
    k_gemm_tc<2><<<gg, 256>>>(N, fc21_b, conv21_b, fc22_b, fc23_b,
                              bn2_g, bn2_b, bn2_m, bn2_v);
    k_agg2<<<(N * 32 + 255) / 256, 256>>>(N);
    k_ep2<<<N, 192>>>(conv21_b, bn2_g, bn2_b, bn2_m, bn2_v, N);

    // pooling + head
    k_pool<<<G, 192>>>(batch, N);
    k_head<<<(G * 32 + 255) / 256, 256>>>(fc2_w, fc2_b, out, G);
}

// round 4
// speedup vs baseline: 1.8372x; 1.1293x over previous
#include <cuda_runtime.h>
#include <cuda_bf16.h>
#include <stdint.h>

// ---------------- problem constants ----------------
#define MAXN 50000
#define MAXE 1600000
#define MAXG 1024

// ---------------- device scratch ----------------
__device__ int   g_is64;
__device__ int   g_deg[MAXN];
__device__ int   g_rowptr[MAXN + 1];
__device__ int   g_cursor[MAXN];
__device__ int   g_bsum[64];
__device__ int   g_boff[64];
__device__ int   g_col[MAXE];
__device__ float g_agg1[MAXN * 32];
__device__ float g_xa[MAXN * 64];
__device__ float g_W1[64 * 384];
__device__ float g_W2[192 * 384];
__device__ float g_h1[(size_t)MAXN * 192];
__device__ float g_lin[(size_t)MAXN * 128];          // relu(fc21) part of block 2
__device__ float g_cprod[(size_t)MAXN * 64];         // relu(fc22)*relu(fc23)
__device__ __nv_bfloat16 g_m2h[(size_t)MAXN * 128];  // raw conv21 messages (bf16)
__device__ float g_h2[(size_t)MAXN * 192];
__device__ float g_pool[MAXG * 384];

// ---------------- index decode (int64 vs int32, runtime-detected) ----------
__device__ __forceinline__ int ld_index(const void* p, long long i) {
    if (g_is64) return (int)((const long long*)p)[i];
    return ((const int*)p)[i];
}

__global__ void k_detect(const unsigned int* ei) {
    if (blockIdx.x == 0 && threadIdx.x == 0) {
        int ok = 1;
        for (int i = 1; i < 64; i += 2)
            if (ei[i] != 0u) ok = 0;
        g_is64 = ok;
    }
}

__global__ void k_zero_deg(int n) {
    int i = blockIdx.x * blockDim.x + threadIdx.x;
    if (i < n) g_deg[i] = 0;
}

__global__ void k_hist(const void* ei, int E) {
    int i = blockIdx.x * blockDim.x + threadIdx.x;
    if (i < E) {
        int d = ld_index(ei, (long long)E + i);   // dst row
        atomicAdd(&g_deg[d], 1);
    }
}

// ---------------- multi-block scan ----------------
__global__ void k_scan_a(int n) {
    __shared__ int wsum[32];
    int tid = threadIdx.x;
    int i = blockIdx.x * 1024 + tid;
    int lane = tid & 31, warp = tid >> 5;
    int v = (i < n) ? g_deg[i] : 0;
    int s = v;
#pragma unroll
    for (int off = 1; off < 32; off <<= 1) {
        int t = __shfl_up_sync(0xffffffffu, s, off);
        if (lane >= off) s += t;
    }
    if (lane == 31) wsum[warp] = s;
    __syncthreads();
    if (warp == 0) {
        int w = wsum[lane];
        int ws = w;
#pragma unroll
        for (int off = 1; off < 32; off <<= 1) {
            int t = __shfl_up_sync(0xffffffffu, ws, off);
            if (lane >= off) ws += t;
        }
        wsum[lane] = ws - w;
        if (lane == 31) g_bsum[blockIdx.x] = ws;
    }
    __syncthreads();
    if (i < n) g_rowptr[i] = (s - v) + wsum[warp];
}

__global__ void k_scan_b(int nb) {
    int tid = threadIdx.x;  // 64 threads
    int v = (tid < nb) ? g_bsum[tid] : 0;
    int s = v;
    int lane = tid & 31, warp = tid >> 5;
    __shared__ int wsum[2];
#pragma unroll
    for (int off = 1; off < 32; off <<= 1) {
        int t = __shfl_up_sync(0xffffffffu, s, off);
        if (lane >= off) s += t;
    }
    if (lane == 31) wsum[warp] = s;
    __syncthreads();
    int add = (warp == 1) ? wsum[0] : 0;
    if (tid < nb) g_boff[tid] = (s - v) + add;
}

__global__ void k_scan_c(int n, int E) {
    int i = blockIdx.x * blockDim.x + threadIdx.x;
    if (i < n) {
        int r = g_rowptr[i] + g_boff[i >> 10];
        g_rowptr[i] = r;
        g_cursor[i] = r;
    }
    if (i == 0) g_rowptr[n] = E;
}

__global__ void k_fill(const void* ei, int E) {
    int i = blockIdx.x * blockDim.x + threadIdx.x;
    if (i < E) {
        int s = ld_index(ei, i);
        int d = ld_index(ei, (long long)E + i);
        int p = atomicAdd(&g_cursor[d], 1);
        g_col[p] = s;
    }
}

// agg1[v] = sum_{u->v} x[u]  (32 dims; warp per node, lane = feature, unroll 4)
__global__ void k_agg1(const float* __restrict__ x, int N) {
    int w = (blockIdx.x * blockDim.x + threadIdx.x) >> 5;
    int lane = threadIdx.x & 31;
    if (w >= N) return;
    int e0 = g_rowptr[w], e1 = g_rowptr[w + 1];
    float acc = 0.f;
    int e = e0;
    for (; e + 4 <= e1; e += 4) {
        int s0 = g_col[e], s1 = g_col[e + 1], s2 = g_col[e + 2], s3 = g_col[e + 3];
        float v0 = __ldg(&x[s0 * 32 + lane]);
        float v1 = __ldg(&x[s1 * 32 + lane]);
        float v2 = __ldg(&x[s2 * 32 + lane]);
        float v3 = __ldg(&x[s3 * 32 + lane]);
        acc += (v0 + v1) + (v2 + v3);
    }
    for (; e < e1; e++) acc += __ldg(&x[g_col[e] * 32 + lane]);
    g_agg1[w * 32 + lane] = acc;
}

// xa = [x | agg1]  (N x 64)
__global__ void k_pack_xa(const float* __restrict__ x, int N) {
    int i = blockIdx.x * blockDim.x + threadIdx.x;
    if (i >= N * 64) return;
    int n = i >> 6, k = i & 63;
    g_xa[i] = (k < 32) ? x[n * 32 + k] : g_agg1[n * 32 + (k - 32)];
}

// W1 pack [64 x 384], paired halves per 128-col slice
__global__ void k_pack_w1(const float* fc11, const float* conv11,
                          const float* fc12, const float* fc13) {
    int i = blockIdx.x * blockDim.x + threadIdx.x;
    if (i >= 64 * 384) return;
    int k = i / 384, m = i % 384;
    int s = m >> 7, l = m & 127, half = l >> 6, c = l & 63;
    float v = 0.f;
    if (s < 2) {
        int ch = s * 64 + c;
        if (half == 0) { if (k < 32) v = fc11[k * 128 + ch]; }
        else           { if (k >= 32) v = conv11[(k - 32) * 128 + ch]; }
    } else {
        if (k < 32) v = half ? fc13[k * 64 + c] : fc12[k * 64 + c];
    }
    g_W1[i] = v;
}

// W2 pack [192 x 384], same paired layout
__global__ void k_pack_w2(const float* fc21, const float* conv21,
                          const float* fc22, const float* fc23) {
    int i = blockIdx.x * blockDim.x + threadIdx.x;
    if (i >= 192 * 384) return;
    int k = i / 384, m = i % 384;
    int s = m >> 7, l = m & 127, half = l >> 6, c = l & 63;
    float v;
    if (s < 2) {
        int ch = s * 64 + c;
        v = half ? conv21[k * 128 + ch] : fc21[k * 128 + ch];
    } else {
        v = half ? fc23[k * 64 + c] : fc22[k * 64 + c];
    }
    g_W2[i] = v;
}

// ---------------- TF32 tensor-core GEMM w/ fused epilogue ----------------
__device__ __forceinline__ uint32_t f2tf32(float f) {
    uint32_t u;
    asm("cvt.rna.tf32.f32 %0, %1;" : "=r"(u) : "f"(f));
    return u;
}

__device__ __forceinline__ void mma_tf32(float& d0, float& d1, float& d2, float& d3,
                                         uint32_t a0, uint32_t a1, uint32_t a2, uint32_t a3,
                                         uint32_t b0, uint32_t b1) {
    asm volatile("mma.sync.aligned.m16n8k8.row.col.f32.tf32.tf32.f32 "
                 "{%0,%1,%2,%3},{%4,%5,%6,%7},{%8,%9},{%0,%1,%2,%3};\n"
                 : "+f"(d0), "+f"(d1), "+f"(d2), "+f"(d3)
                 : "r"(a0), "r"(a1), "r"(a2), "r"(a3), "r"(b0), "r"(b1));
}

// C[N,384] = A[N,K] @ W[K,384]. Block tile 128 rows x 128 cols (slice s).
// MODE 1: epilogue -> g_h1 (bias+relu+combine+BN fused)
// MODE 2: epilogue -> g_lin (relu'd), g_m2h (raw, bf16), g_cprod
template <int MODE>
__global__ __launch_bounds__(256, 2) void k_gemm_tc(
    int N,
    const float* __restrict__ bL1, const float* __restrict__ bR1,
    const float* __restrict__ bL2, const float* __restrict__ bR2,
    const float* __restrict__ bng, const float* __restrict__ bnb,
    const float* __restrict__ bnm, const float* __restrict__ bnv) {
    constexpr int K = (MODE == 1) ? 64 : 192;
    const float* __restrict__ A = (MODE == 1) ? g_xa : g_h1;
    const float* __restrict__ W = (MODE == 1) ? g_W1 : g_W2;

    __shared__ uint32_t As[128 * 12];
    __shared__ uint32_t Ws[128 * 12];

    const int rowBase = blockIdx.x * 128;
    const int s = blockIdx.y;          // col slice 0..2
    const int colBase = s * 128;
    const int tid = threadIdx.x;
    const int warp = tid >> 5, lane = tid & 31;
    const int wm = warp >> 2, wn = warp & 3;
    const int gq = lane >> 2, tq = lane & 3;

    float acc[4][4][4];
#pragma unroll
    for (int i = 0; i < 4; i++)
#pragma unroll
        for (int j = 0; j < 4; j++)
#pragma unroll
            for (int c = 0; c < 4; c++) acc[i][j][c] = 0.f;

    const int ar = tid >> 1, ah = tid & 1;
    const int wc = tid & 127, wkp = tid >> 7;

    for (int k0 = 0; k0 < K; k0 += 8) {
        int gr = rowBase + ar;
        if (gr >= N) gr = N - 1;
        float4 av = *(const float4*)(A + (size_t)gr * K + k0 + ah * 4);
        uint32_t* ad = &As[ar * 12 + ah * 4];
        ad[0] = f2tf32(av.x); ad[1] = f2tf32(av.y);
        ad[2] = f2tf32(av.z); ad[3] = f2tf32(av.w);
#pragma unroll
        for (int i = 0; i < 4; i++) {
            float wv = W[(size_t)(k0 + wkp * 4 + i) * 384 + colBase + wc];
            Ws[wc * 12 + wkp * 4 + i] = f2tf32(wv);
        }
        __syncthreads();

        uint32_t af[4][4], bf[4][2];
#pragma unroll
        for (int i = 0; i < 4; i++) {
            int m0 = wm * 64 + i * 16;
            af[i][0] = As[(m0 + gq) * 12 + tq];
            af[i][1] = As[(m0 + gq + 8) * 12 + tq];
            af[i][2] = As[(m0 + gq) * 12 + tq + 4];
            af[i][3] = As[(m0 + gq + 8) * 12 + tq + 4];
        }
#pragma unroll
        for (int j = 0; j < 4; j++) {
            int n0 = ((j < 2) ? 0 : 64) + wn * 16 + (j & 1) * 8;
            bf[j][0] = Ws[(n0 + gq) * 12 + tq];
            bf[j][1] = Ws[(n0 + gq) * 12 + tq + 4];
        }
#pragma unroll
        for (int i = 0; i < 4; i++)
#pragma unroll
            for (int j = 0; j < 4; j++)
                mma_tf32(acc[i][j][0], acc[i][j][1], acc[i][j][2], acc[i][j][3],
                         af[i][0], af[i][1], af[i][2], af[i][3],
                         bf[j][0], bf[j][1]);
        __syncthreads();
    }

    // fused epilogue: pairs are (acc[i][j][*], acc[i][j+2][*]) for j=0,1
#pragma unroll
    for (int i = 0; i < 4; i++) {
#pragma unroll
        for (int j = 0; j < 2; j++) {
            int l = wn * 16 + j * 8 + tq * 2;  // local col in [0,64)
#pragma unroll
            for (int p = 0; p < 2; p++) {
                int n = rowBase + wm * 64 + i * 16 + gq + p * 8;
                if (n >= N) continue;
                float o0, o1;
                if (s < 2) {
                    int ch = s * 64 + l;
                    float L0 = acc[i][j][p * 2 + 0], L1 = acc[i][j][p * 2 + 1];
                    float R0 = acc[i][j + 2][p * 2 + 0], R1 = acc[i][j + 2][p * 2 + 1];
                    if (MODE == 1) {
                        float v0 = fmaxf(L0 + __ldg(&bL1[ch]), 0.f) +
                                   fmaxf(R0 + __ldg(&bR1[ch]), 0.f);
                        float v1 = fmaxf(L1 + __ldg(&bL1[ch + 1]), 0.f) +
                                   fmaxf(R1 + __ldg(&bR1[ch + 1]), 0.f);
                        o0 = __ldg(&bng[ch]) * (v0 - __ldg(&bnm[ch])) *
                                 rsqrtf(__ldg(&bnv[ch]) + 1e-5f) + __ldg(&bnb[ch]);
                        o1 = __ldg(&bng[ch + 1]) * (v1 - __ldg(&bnm[ch + 1])) *
                                 rsqrtf(__ldg(&bnv[ch + 1]) + 1e-5f) + __ldg(&bnb[ch + 1]);
                        *(float2*)(g_h1 + (size_t)n * 192 + ch) = make_float2(o0, o1);
                    } else {
                        float r0 = fmaxf(L0 + __ldg(&bL1[ch]), 0.f);
                        float r1 = fmaxf(L1 + __ldg(&bL1[ch + 1]), 0.f);
                        *(float2*)(g_lin + (size_t)n * 128 + ch) = make_float2(r0, r1);
                        *(__nv_bfloat162*)(g_m2h + (size_t)n * 128 + ch) =
                            __floats2bfloat162_rn(R0, R1);
                    }
                } else {
                    float L0 = acc[i][j][p * 2 + 0], L1 = acc[i][j][p * 2 + 1];
                    float R0 = acc[i][j + 2][p * 2 + 0], R1 = acc[i][j + 2][p * 2 + 1];
                    float v0 = fmaxf(L0 + __ldg(&bL2[l]), 0.f) *
                               fmaxf(R0 + __ldg(&bR2[l]), 0.f);
                    float v1 = fmaxf(L1 + __ldg(&bL2[l + 1]), 0.f) *
                               fmaxf(R1 + __ldg(&bR2[l + 1]), 0.f);
                    if (MODE == 1) {
                        int ch = 128 + l;
                        o0 = __ldg(&bng[ch]) * (v0 - __ldg(&bnm[ch])) *
                                 rsqrtf(__ldg(&bnv[ch]) + 1e-5f) + __ldg(&bnb[ch]);
                        o1 = __ldg(&bng[ch + 1]) * (v1 - __ldg(&bnm[ch + 1])) *
                                 rsqrtf(__ldg(&bnv[ch + 1]) + 1e-5f) + __ldg(&bnb[ch + 1]);
                        *(float2*)(g_h1 + (size_t)n * 192 + ch) = make_float2(o0, o1);
                    } else {
                        *(float2*)(g_cprod + (size_t)n * 64 + l) = make_float2(v0, v1);
                    }
                }
            }
        }
    }
}

// Fused: agg2[v] = sum_{u->v} m2h[u]  (bf16 gather, fp32 accumulate),
// then full block-2 epilogue (lin + relu(agg+bias), cprod, BN) -> h2.
// Warp per node; lane owns channels [lane*4, lane*4+4).
__global__ void k_agg2_ep2(const float* __restrict__ conv21_b,
                           const float* __restrict__ gg, const float* __restrict__ bb,
                           const float* __restrict__ mm, const float* __restrict__ vv,
                           int N) {
    int w = (blockIdx.x * blockDim.x + threadIdx.x) >> 5;
    int lane = threadIdx.x & 31;
    if (w >= N) return;
    int e0 = g_rowptr[w], e1 = g_rowptr[w + 1];
    float a0 = 0.f, a1 = 0.f, a2 = 0.f, a3 = 0.f;
    int e = e0;
    for (; e + 4 <= e1; e += 4) {
        int s0 = g_col[e], s1 = g_col[e + 1], s2 = g_col[e + 2], s3 = g_col[e + 3];
        uint2 u0 = *(const uint2*)(g_m2h + (size_t)s0 * 128 + lane * 4);
        uint2 u1 = *(const uint2*)(g_m2h + (size_t)s1 * 128 + lane * 4);
        uint2 u2 = *(const uint2*)(g_m2h + (size_t)s2 * 128 + lane * 4);
        uint2 u3 = *(const uint2*)(g_m2h + (size_t)s3 * 128 + lane * 4);
#pragma unroll
        for (int q = 0; q < 4; q++) {
            uint2 u = (q == 0) ? u0 : (q == 1) ? u1 : (q == 2) ? u2 : u3;
            float2 lo = __bfloat1622float2(*(__nv_bfloat162*)&u.x);
            float2 hi = __bfloat1622float2(*(__nv_bfloat162*)&u.y);
            a0 += lo.x; a1 += lo.y; a2 += hi.x; a3 += hi.y;
        }
    }
    for (; e < e1; e++) {
        int sc = g_col[e];
        uint2 u = *(const uint2*)(g_m2h + (size_t)sc * 128 + lane * 4);
        float2 lo = __bfloat1622float2(*(__nv_bfloat162*)&u.x);
        float2 hi = __bfloat1622float2(*(__nv_bfloat162*)&u.y);
        a0 += lo.x; a1 += lo.y; a2 += hi.x; a3 += hi.y;
    }
    // epilogue: channels c0..c0+3
    int c0 = lane * 4;
    float4 lb = *(const float4*)(g_lin + (size_t)w * 128 + c0);
    float4 cb = *(const float4*)(conv21_b + c0);
    float v0 = lb.x + fmaxf(a0 + cb.x, 0.f);
    float v1 = lb.y + fmaxf(a1 + cb.y, 0.f);
    float v2 = lb.z + fmaxf(a2 + cb.z, 0.f);
    float v3 = lb.w + fmaxf(a3 + cb.w, 0.f);
    float4 G = *(const float4*)(gg + c0);
    float4 B = *(const float4*)(bb + c0);
    float4 M = *(const float4*)(mm + c0);
    float4 V = *(const float4*)(vv + c0);
    float4 o;
    o.x = G.x * (v0 - M.x) * rsqrtf(V.x + 1e-5f) + B.x;
    o.y = G.y * (v1 - M.y) * rsqrtf(V.y + 1e-5f) + B.y;
    o.z = G.z * (v2 - M.z) * rsqrtf(V.z + 1e-5f) + B.z;
    o.w = G.w * (v3 - M.w) * rsqrtf(V.w + 1e-5f) + B.w;
    *(float4*)(g_h2 + (size_t)w * 192 + c0) = o;
    // cprod channels 128..191: lanes 0..15 handle 4 each
    if (lane < 16) {
        int l = lane * 4, ch = 128 + l;
        float4 cp = *(const float4*)(g_cprod + (size_t)w * 64 + l);
        float4 G2 = *(const float4*)(gg + ch);
        float4 B2 = *(const float4*)(bb + ch);
        float4 M2 = *(const float4*)(mm + ch);
        float4 V2 = *(const float4*)(vv + ch);
        float4 o2;
        o2.x = G2.x * (cp.x - M2.x) * rsqrtf(V2.x + 1e-5f) + B2.x;
        o2.y = G2.y * (cp.y - M2.y) * rsqrtf(V2.y + 1e-5f) + B2.y;
        o2.z = G2.z * (cp.z - M2.z) * rsqrtf(V2.z + 1e-5f) + B2.z;
        o2.w = G2.w * (cp.w - M2.w) * rsqrtf(V2.w + 1e-5f) + B2.w;
        *(float4*)(g_h2 + (size_t)w * 192 + ch) = o2;
    }
}

// ---------------- pooling (batch is sorted) ----------------
__device__ __forceinline__ int lb_batch(const void* batch, int n, long long val) {
    int lo = 0, hi = n;
    while (lo < hi) {
        int mid = (lo + hi) >> 1;
        long long b = g_is64 ? ((const long long*)batch)[mid]
                             : (long long)((const int*)batch)[mid];
        if (b < val) lo = mid + 1; else hi = mid;
    }
    return lo;
}

__global__ void k_pool(const void* batch, int N) {
    int g = blockIdx.x;
    __shared__ int slo, shi;
    if (threadIdx.x == 0) {
        slo = lb_batch(batch, N, (long long)g);
        shi = lb_batch(batch, N, (long long)g + 1);
    }
    __syncthreads();
    int lo = slo, hi = shi;
    int ch = threadIdx.x;  // 192
    float sum = 0.f, mx = -3.402823466e38f;
    for (int n = lo; n < hi; n++) {
        float v = g_h2[(size_t)n * 192 + ch];
        sum += v;
        mx = fmaxf(mx, v);
    }
    int cnt = hi - lo;
    g_pool[g * 384 + ch] = sum / fmaxf((float)cnt, 1.f);
    g_pool[g * 384 + 192 + ch] = (cnt > 0) ? mx : 0.f;
}

// ---------------- head: logits + log_softmax ----------------
__global__ void k_head(const float* __restrict__ w, const float* __restrict__ b,
                       float* __restrict__ out, int G) {
    int t = blockIdx.x * blockDim.x + threadIdx.x;
    int warp = t >> 5, lane = t & 31;
    if (warp >= G) return;
    float lg[6] = {0.f, 0.f, 0.f, 0.f, 0.f, 0.f};
    for (int k = lane; k < 384; k += 32) {
        float gv = g_pool[warp * 384 + k];
#pragma unroll
        for (int j = 0; j < 6; j++) lg[j] += gv * w[k * 6 + j];
    }
#pragma unroll
    for (int off = 16; off; off >>= 1)
#pragma unroll
        for (int j = 0; j < 6; j++) lg[j] += __shfl_xor_sync(0xffffffffu, lg[j], off);
    if (lane == 0) {
        float v[6];
        float mx = -3.402823466e38f;
#pragma unroll
        for (int j = 0; j < 6; j++) { v[j] = lg[j] + b[j]; mx = fmaxf(mx, v[j]); }
        float s = 0.f;
#pragma unroll
        for (int j = 0; j < 6; j++) s += expf(v[j] - mx);
        float lse = mx + logf(s);
#pragma unroll
        for (int j = 0; j < 6; j++) out[warp * 6 + j] = v[j] - lse;
    }
}

// ---------------- launch ----------------
extern "C" void kernel_launch(void* const* d_in, const int* in_sizes, int n_in,
                              void* d_out, int out_size) {
    int base = (n_in >= 30) ? 4 : 3;
    const float* x        = (const float*)d_in[0];
    const void*  ei       = d_in[1];
    const void*  batch    = d_in[2];
    const float* fc11_w   = (const float*)d_in[base + 0];
    const float* fc11_b   = (const float*)d_in[base + 1];
    const float* conv11_w = (const float*)d_in[base + 2];
    const float* conv11_b = (const float*)d_in[base + 3];
    const float* fc12_w   = (const float*)d_in[base + 4];
    const float* fc12_b   = (const float*)d_in[base + 5];
    const float* fc13_w   = (const float*)d_in[base + 6];
    const float* fc13_b   = (const float*)d_in[base + 7];
    const float* bn1_g    = (const float*)d_in[base + 8];
    const float* bn1_b    = (const float*)d_in[base + 9];
    const float* bn1_m    = (const float*)d_in[base + 10];
    const float* bn1_v    = (const float*)d_in[base + 11];
    const float* fc21_w   = (const float*)d_in[base + 12];
    const float* fc21_b   = (const float*)d_in[base + 13];
    const float* conv21_w = (const float*)d_in[base + 14];
    const float* conv21_b = (const float*)d_in[base + 15];
    const float* fc22_w   = (const float*)d_in[base + 16];
    const float* fc22_b   = (const float*)d_in[base + 17];
    const float* fc23_w   = (const float*)d_in[base + 18];
    const float* fc23_b   = (const float*)d_in[base + 19];
    const float* bn2_g    = (const float*)d_in[base + 20];
    const float* bn2_b    = (const float*)d_in[base + 21];
    const float* bn2_m    = (const float*)d_in[base + 22];
    const float* bn2_v    = (const float*)d_in[base + 23];
    const float* fc2_w    = (const float*)d_in[base + 24];
    const float* fc2_b    = (const float*)d_in[base + 25];

    int N = in_sizes[0] / 32;
    int E = in_sizes[1] / 2;
    int G = out_size / 6;
    float* out = (float*)d_out;

    // CSR build
    k_detect<<<1, 32>>>((const unsigned int*)ei);
    k_zero_deg<<<(N + 255) / 256, 256>>>(N);
    k_hist<<<(E + 255) / 256, 256>>>(ei, E);
    int nb = (N + 1023) / 1024;
    k_scan_a<<<nb, 1024>>>(N);
    k_scan_b<<<1, 64>>>(nb);
    k_scan_c<<<(N + 255) / 256, 256>>>(N, E);
    k_fill<<<(E + 255) / 256, 256>>>(ei, E);

    // block 1: aggregate raw feats, pack, fused GEMM -> h1
    k_agg1<<<(N * 32 + 255) / 256, 256>>>(x, N);
    k_pack_xa<<<(N * 64 + 255) / 256, 256>>>(x, N);
    k_pack_w1<<<(64 * 384 + 255) / 256, 256>>>(fc11_w, conv11_w, fc12_w, fc13_w);
    k_pack_w2<<<(192 * 384 + 255) / 256, 256>>>(fc21_w, conv21_w, fc22_w, fc23_w);
    dim3 gg((N + 127) / 128, 3);
    k_gemm_tc<1><<<gg, 256>>>(N, fc11_b, conv11_b, fc12_b, fc13_b,
                              bn1_g, bn1_b, bn1_m, bn1_v);

    // block 2: fused GEMM -> lin/m2h/cprod, fused aggregate+epilogue -> h2
    k_gemm_tc<2><<<gg, 256>>>(N, fc21_b, conv21_b, fc22_b, fc23_b,
                              bn2_g, bn2_b, bn2_m, bn2_v);
    k_agg2_ep2<<<(N * 32 + 255) / 256, 256>>>(conv21_b, bn2_g, bn2_b, bn2_m, bn2_v, N);

    // pooling + head
    k_pool<<<G, 192>>>(batch, N);
    k_head<<<(G * 32 + 255) / 256, 256>>>(fc2_w, fc2_b, out, G);
}

// round 5
// speedup vs baseline: 2.0005x; 1.0889x over previous
#include <cuda_runtime.h>
#include <cuda_bf16.h>
#include <stdint.h>

// ---------------- problem constants ----------------
#define MAXN 50000
#define MAXE 1600000
#define MAXG 1024

// ---------------- device scratch ----------------
__device__ int   g_is64;
__device__ int   g_deg[MAXN];
__device__ int   g_rowptr[MAXN + 1];
__device__ int   g_cursor[MAXN];
__device__ int   g_bsum[64];
__device__ int   g_boff[64];
__device__ int   g_col[MAXE];
__device__ __nv_bfloat16 g_xh[MAXN * 32];            // bf16 copy of x for agg1
__device__ float g_xa[MAXN * 64];
__device__ float g_W1[64 * 384];
__device__ float g_W2[192 * 384];
__device__ float g_h1[(size_t)MAXN * 192];
__device__ float g_lin[(size_t)MAXN * 128];          // relu(fc21) part of block 2
__device__ float g_cprod[(size_t)MAXN * 64];         // relu(fc22)*relu(fc23)
__device__ __nv_bfloat16 g_m2h[(size_t)MAXN * 128];  // raw conv21 messages (bf16)
__device__ float g_h2[(size_t)MAXN * 192];
__device__ float g_pool[MAXG * 384];

// ---------------- index decode (int64 vs int32, runtime-detected) ----------
__device__ __forceinline__ int ld_index(const void* p, long long i) {
    if (g_is64) return (int)((const long long*)p)[i];
    return ((const int*)p)[i];
}

// Fused init: dtype detect, degree zero, weight packs, x -> bf16 convert.
__global__ void k_init(const unsigned int* __restrict__ ei,
                       const float* __restrict__ x,
                       const float* __restrict__ fc11, const float* __restrict__ conv11,
                       const float* __restrict__ fc12, const float* __restrict__ fc13,
                       const float* __restrict__ fc21, const float* __restrict__ conv21,
                       const float* __restrict__ fc22, const float* __restrict__ fc23,
                       int N) {
    int i = blockIdx.x * blockDim.x + threadIdx.x;
    if (i == 0) {
        int ok = 1;
        for (int q = 1; q < 64; q += 2)
            if (ei[q] != 0u) ok = 0;
        g_is64 = ok;
    }
    if (i < N) g_deg[i] = 0;
    if (i < N * 32) g_xh[i] = __float2bfloat16(x[i]);
    if (i < 64 * 384) {
        int k = i / 384, m = i % 384;
        int s = m >> 7, l = m & 127, half = l >> 6, c = l & 63;
        float v = 0.f;
        if (s < 2) {
            int ch = s * 64 + c;
            if (half == 0) { if (k < 32) v = fc11[k * 128 + ch]; }
            else           { if (k >= 32) v = conv11[(k - 32) * 128 + ch]; }
        } else {
            if (k < 32) v = half ? fc13[k * 64 + c] : fc12[k * 64 + c];
        }
        g_W1[i] = v;
    }
    if (i < 192 * 384) {
        int k = i / 384, m = i % 384;
        int s = m >> 7, l = m & 127, half = l >> 6, c = l & 63;
        float v;
        if (s < 2) {
            int ch = s * 64 + c;
            v = half ? conv21[k * 128 + ch] : fc21[k * 128 + ch];
        } else {
            v = half ? fc23[k * 64 + c] : fc22[k * 64 + c];
        }
        g_W2[i] = v;
    }
}

__global__ void k_hist(const void* ei, int E) {
    int i = blockIdx.x * blockDim.x + threadIdx.x;
    if (i < E) {
        int d = ld_index(ei, (long long)E + i);   // dst row
        atomicAdd(&g_deg[d], 1);
    }
}

// ---------------- multi-block scan ----------------
__global__ void k_scan_a(int n) {
    __shared__ int wsum[32];
    int tid = threadIdx.x;
    int i = blockIdx.x * 1024 + tid;
    int lane = tid & 31, warp = tid >> 5;
    int v = (i < n) ? g_deg[i] : 0;
    int s = v;
#pragma unroll
    for (int off = 1; off < 32; off <<= 1) {
        int t = __shfl_up_sync(0xffffffffu, s, off);
        if (lane >= off) s += t;
    }
    if (lane == 31) wsum[warp] = s;
    __syncthreads();
    if (warp == 0) {
        int w = wsum[lane];
        int ws = w;
#pragma unroll
        for (int off = 1; off < 32; off <<= 1) {
            int t = __shfl_up_sync(0xffffffffu, ws, off);
            if (lane >= off) ws += t;
        }
        wsum[lane] = ws - w;
        if (lane == 31) g_bsum[blockIdx.x] = ws;
    }
    __syncthreads();
    if (i < n) g_rowptr[i] = (s - v) + wsum[warp];
}

__global__ void k_scan_b(int nb) {
    int tid = threadIdx.x;  // 64 threads
    int v = (tid < nb) ? g_bsum[tid] : 0;
    int s = v;
    int lane = tid & 31, warp = tid >> 5;
    __shared__ int wsum[2];
#pragma unroll
    for (int off = 1; off < 32; off <<= 1) {
        int t = __shfl_up_sync(0xffffffffu, s, off);
        if (lane >= off) s += t;
    }
    if (lane == 31) wsum[warp] = s;
    __syncthreads();
    int add = (warp == 1) ? wsum[0] : 0;
    if (tid < nb) g_boff[tid] = (s - v) + add;
}

__global__ void k_scan_c(int n, int E) {
    int i = blockIdx.x * blockDim.x + threadIdx.x;
    if (i < n) {
        int r = g_rowptr[i] + g_boff[i >> 10];
        g_rowptr[i] = r;
        g_cursor[i] = r;
    }
    if (i == 0) g_rowptr[n] = E;
}

__global__ void k_fill(const void* ei, int E) {
    int i = blockIdx.x * blockDim.x + threadIdx.x;
    if (i < E) {
        int s = ld_index(ei, i);
        int d = ld_index(ei, (long long)E + i);
        int p = atomicAdd(&g_cursor[d], 1);
        g_col[p] = s;
    }
}

// agg1 + xa pack. Warp per node:
//   all lanes: copy x fp32 -> xa[0:32]
//   gather bf16 x rows (64 B each); lanes 0..15 own channel pairs 2*ln, accumulate fp32
__global__ void k_agg1(const float* __restrict__ x, int N) {
    int w = (blockIdx.x * blockDim.x + threadIdx.x) >> 5;
    int lane = threadIdx.x & 31;
    if (w >= N) return;
    g_xa[w * 64 + lane] = x[w * 32 + lane];
    int ln = lane & 15;
    int e0 = g_rowptr[w], e1 = g_rowptr[w + 1];
    float a0 = 0.f, a1 = 0.f;
    int e = e0;
    for (; e + 4 <= e1; e += 4) {
        int s0 = g_col[e], s1 = g_col[e + 1], s2 = g_col[e + 2], s3 = g_col[e + 3];
        float2 f0 = __bfloat1622float2(*(const __nv_bfloat162*)(g_xh + s0 * 32 + ln * 2));
        float2 f1 = __bfloat1622float2(*(const __nv_bfloat162*)(g_xh + s1 * 32 + ln * 2));
        float2 f2 = __bfloat1622float2(*(const __nv_bfloat162*)(g_xh + s2 * 32 + ln * 2));
        float2 f3 = __bfloat1622float2(*(const __nv_bfloat162*)(g_xh + s3 * 32 + ln * 2));
        a0 += (f0.x + f1.x) + (f2.x + f3.x);
        a1 += (f0.y + f1.y) + (f2.y + f3.y);
    }
    for (; e < e1; e++) {
        int sc = g_col[e];
        float2 f = __bfloat1622float2(*(const __nv_bfloat162*)(g_xh + sc * 32 + ln * 2));
        a0 += f.x; a1 += f.y;
    }
    if (lane < 16)
        *(float2*)(g_xa + (size_t)w * 64 + 32 + ln * 2) = make_float2(a0, a1);
}

// ---------------- TF32 tensor-core GEMM w/ fused epilogue ----------------
__device__ __forceinline__ uint32_t f2tf32(float f) {
    uint32_t u;
    asm("cvt.rna.tf32.f32 %0, %1;" : "=r"(u) : "f"(f));
    return u;
}

__device__ __forceinline__ void mma_tf32(float& d0, float& d1, float& d2, float& d3,
                                         uint32_t a0, uint32_t a1, uint32_t a2, uint32_t a3,
                                         uint32_t b0, uint32_t b1) {
    asm volatile("mma.sync.aligned.m16n8k8.row.col.f32.tf32.tf32.f32 "
                 "{%0,%1,%2,%3},{%4,%5,%6,%7},{%8,%9},{%0,%1,%2,%3};\n"
                 : "+f"(d0), "+f"(d1), "+f"(d2), "+f"(d3)
                 : "r"(a0), "r"(a1), "r"(a2), "r"(a3), "r"(b0), "r"(b1));
}

// C[N,384] = A[N,K] @ W[K,384], double-buffered smem (1 sync / k-chunk).
// MODE 1: epilogue -> g_h1; MODE 2: epilogue -> g_lin / g_m2h / g_cprod
template <int MODE>
__global__ __launch_bounds__(256, 2) void k_gemm_tc(
    int N,
    const float* __restrict__ bL1, const float* __restrict__ bR1,
    const float* __restrict__ bL2, const float* __restrict__ bR2,
    const float* __restrict__ bng, const float* __restrict__ bnb,
    const float* __restrict__ bnm, const float* __restrict__ bnv) {
    constexpr int K = (MODE == 1) ? 64 : 192;
    constexpr int NK = K / 8;
    const float* __restrict__ A = (MODE == 1) ? g_xa : g_h1;
    const float* __restrict__ W = (MODE == 1) ? g_W1 : g_W2;

    __shared__ uint32_t As[2][128 * 12];
    __shared__ uint32_t Ws[2][128 * 12];

    const int rowBase = blockIdx.x * 128;
    const int s = blockIdx.y;          // col slice 0..2
    const int colBase = s * 128;
    const int tid = threadIdx.x;
    const int warp = tid >> 5, lane = tid & 31;
    const int wm = warp >> 2, wn = warp & 3;
    const int gq = lane >> 2, tq = lane & 3;

    float acc[4][4][4];
#pragma unroll
    for (int i = 0; i < 4; i++)
#pragma unroll
        for (int j = 0; j < 4; j++)
#pragma unroll
            for (int c = 0; c < 4; c++) acc[i][j][c] = 0.f;

    const int ar = tid >> 1, ah = tid & 1;
    const int wc = tid & 127, wkp = tid >> 7;
    int gr = rowBase + ar;
    if (gr >= N) gr = N - 1;
    const float* Arow = A + (size_t)gr * K + ah * 4;
    const float* Wcol = W + colBase + wc;

    // prologue: stage chunk 0 -> buffer 0
    {
        float4 av = *(const float4*)(Arow);
        uint32_t* ad = &As[0][ar * 12 + ah * 4];
        ad[0] = f2tf32(av.x); ad[1] = f2tf32(av.y);
        ad[2] = f2tf32(av.z); ad[3] = f2tf32(av.w);
#pragma unroll
        for (int i = 0; i < 4; i++)
            Ws[0][wc * 12 + wkp * 4 + i] = f2tf32(Wcol[(size_t)(wkp * 4 + i) * 384]);
    }
    __syncthreads();

    for (int kc = 0; kc < NK; kc++) {
        const int cur = kc & 1;
        float4 av;
        float wv[4];
        const bool more = (kc + 1 < NK);
        if (more) {
            av = *(const float4*)(Arow + (kc + 1) * 8);
#pragma unroll
            for (int i = 0; i < 4; i++)
                wv[i] = Wcol[(size_t)((kc + 1) * 8 + wkp * 4 + i) * 384];
        }

        uint32_t af[4][4], bf[4][2];
#pragma unroll
        for (int i = 0; i < 4; i++) {
            int m0 = wm * 64 + i * 16;
            af[i][0] = As[cur][(m0 + gq) * 12 + tq];
            af[i][1] = As[cur][(m0 + gq + 8) * 12 + tq];
            af[i][2] = As[cur][(m0 + gq) * 12 + tq + 4];
            af[i][3] = As[cur][(m0 + gq + 8) * 12 + tq + 4];
        }
#pragma unroll
        for (int j = 0; j < 4; j++) {
            int n0 = ((j < 2) ? 0 : 64) + wn * 16 + (j & 1) * 8;
            bf[j][0] = Ws[cur][(n0 + gq) * 12 + tq];
            bf[j][1] = Ws[cur][(n0 + gq) * 12 + tq + 4];
        }
#pragma unroll
        for (int i = 0; i < 4; i++)
#pragma unroll
            for (int j = 0; j < 4; j++)
                mma_tf32(acc[i][j][0], acc[i][j][1], acc[i][j][2], acc[i][j][3],
                         af[i][0], af[i][1], af[i][2], af[i][3],
                         bf[j][0], bf[j][1]);

        if (more) {
            uint32_t* ad = &As[cur ^ 1][ar * 12 + ah * 4];
            ad[0] = f2tf32(av.x); ad[1] = f2tf32(av.y);
            ad[2] = f2tf32(av.z); ad[3] = f2tf32(av.w);
#pragma unroll
            for (int i = 0; i < 4; i++)
                Ws[cur ^ 1][wc * 12 + wkp * 4 + i] = f2tf32(wv[i]);
        }
        __syncthreads();
    }

    // fused epilogue: pairs are (acc[i][j][*], acc[i][j+2][*]) for j=0,1
#pragma unroll
    for (int i = 0; i < 4; i++) {
#pragma unroll
        for (int j = 0; j < 2; j++) {
            int l = wn * 16 + j * 8 + tq * 2;  // local col in [0,64)
#pragma unroll
            for (int p = 0; p < 2; p++) {
                int n = rowBase + wm * 64 + i * 16 + gq + p * 8;
                if (n >= N) continue;
                float o0, o1;
                if (s < 2) {
                    int ch = s * 64 + l;
                    float L0 = acc[i][j][p * 2 + 0], L1 = acc[i][j][p * 2 + 1];
                    float R0 = acc[i][j + 2][p * 2 + 0], R1 = acc[i][j + 2][p * 2 + 1];
                    if (MODE == 1) {
                        float v0 = fmaxf(L0 + __ldg(&bL1[ch]), 0.f) +
                                   fmaxf(R0 + __ldg(&bR1[ch]), 0.f);
                        float v1 = fmaxf(L1 + __ldg(&bL1[ch + 1]), 0.f) +
                                   fmaxf(R1 + __ldg(&bR1[ch + 1]), 0.f);
                        o0 = __ldg(&bng[ch]) * (v0 - __ldg(&bnm[ch])) *
                                 rsqrtf(__ldg(&bnv[ch]) + 1e-5f) + __ldg(&bnb[ch]);
                        o1 = __ldg(&bng[ch + 1]) * (v1 - __ldg(&bnm[ch + 1])) *
                                 rsqrtf(__ldg(&bnv[ch + 1]) + 1e-5f) + __ldg(&bnb[ch + 1]);
                        *(float2*)(g_h1 + (size_t)n * 192 + ch) = make_float2(o0, o1);
                    } else {
                        float r0 = fmaxf(L0 + __ldg(&bL1[ch]), 0.f);
                        float r1 = fmaxf(L1 + __ldg(&bL1[ch + 1]), 0.f);
                        *(float2*)(g_lin + (size_t)n * 128 + ch) = make_float2(r0, r1);
                        *(__nv_bfloat162*)(g_m2h + (size_t)n * 128 + ch) =
                            __floats2bfloat162_rn(R0, R1);
                    }
                } else {
                    float L0 = acc[i][j][p * 2 + 0], L1 = acc[i][j][p * 2 + 1];
                    float R0 = acc[i][j + 2][p * 2 + 0], R1 = acc[i][j + 2][p * 2 + 1];
                    float v0 = fmaxf(L0 + __ldg(&bL2[l]), 0.f) *
                               fmaxf(R0 + __ldg(&bR2[l]), 0.f);
                    float v1 = fmaxf(L1 + __ldg(&bL2[l + 1]), 0.f) *
                               fmaxf(R1 + __ldg(&bR2[l + 1]), 0.f);
                    if (MODE == 1) {
                        int ch = 128 + l;
                        o0 = __ldg(&bng[ch]) * (v0 - __ldg(&bnm[ch])) *
                                 rsqrtf(__ldg(&bnv[ch]) + 1e-5f) + __ldg(&bnb[ch]);
                        o1 = __ldg(&bng[ch + 1]) * (v1 - __ldg(&bnm[ch + 1])) *
                                 rsqrtf(__ldg(&bnv[ch + 1]) + 1e-5f) + __ldg(&bnb[ch + 1]);
                        *(float2*)(g_h1 + (size_t)n * 192 + ch) = make_float2(o0, o1);
                    } else {
                        *(float2*)(g_cprod + (size_t)n * 64 + l) = make_float2(v0, v1);
                    }
                }
            }
        }
    }
}

// Fused: agg2[v] = sum_{u->v} m2h[u] (bf16 gather, fp32 acc) + block-2 epilogue -> h2
__global__ void k_agg2_ep2(const float* __restrict__ conv21_b,
                           const float* __restrict__ gg, const float* __restrict__ bb,
                           const float* __restrict__ mm, const float* __restrict__ vv,
                           int N) {
    int w = (blockIdx.x * blockDim.x + threadIdx.x) >> 5;
    int lane = threadIdx.x & 31;
    if (w >= N) return;
    int e0 = g_rowptr[w], e1 = g_rowptr[w + 1];
    float a0 = 0.f, a1 = 0.f, a2 = 0.f, a3 = 0.f;
    int e = e0;
    for (; e + 4 <= e1; e += 4) {
        int s0 = g_col[e], s1 = g_col[e + 1], s2 = g_col[e + 2], s3 = g_col[e + 3];
        uint2 u0 = *(const uint2*)(g_m2h + (size_t)s0 * 128 + lane * 4);
        uint2 u1 = *(const uint2*)(g_m2h + (size_t)s1 * 128 + lane * 4);
        uint2 u2 = *(const uint2*)(g_m2h + (size_t)s2 * 128 + lane * 4);
        uint2 u3 = *(const uint2*)(g_m2h + (size_t)s3 * 128 + lane * 4);
#pragma unroll
        for (int q = 0; q < 4; q++) {
            uint2 u = (q == 0) ? u0 : (q == 1) ? u1 : (q == 2) ? u2 : u3;
            float2 lo = __bfloat1622float2(*(__nv_bfloat162*)&u.x);
            float2 hi = __bfloat1622float2(*(__nv_bfloat162*)&u.y);
            a0 += lo.x; a1 += lo.y; a2 += hi.x; a3 += hi.y;
        }
    }
    for (; e < e1; e++) {
        int sc = g_col[e];
        uint2 u = *(const uint2*)(g_m2h + (size_t)sc * 128 + lane * 4);
        float2 lo = __bfloat1622float2(*(__nv_bfloat162*)&u.x);
        float2 hi = __bfloat1622float2(*(__nv_bfloat162*)&u.y);
        a0 += lo.x; a1 += lo.y; a2 += hi.x; a3 += hi.y;
    }
    int c0 = lane * 4;
    float4 lb = *(const float4*)(g_lin + (size_t)w * 128 + c0);
    float4 cb = *(const float4*)(conv21_b + c0);
    float v0 = lb.x + fmaxf(a0 + cb.x, 0.f);
    float v1 = lb.y + fmaxf(a1 + cb.y, 0.f);
    float v2 = lb.z + fmaxf(a2 + cb.z, 0.f);
    float v3 = lb.w + fmaxf(a3 + cb.w, 0.f);
    float4 G = *(const float4*)(gg + c0);
    float4 B = *(const float4*)(bb + c0);
    float4 M = *(const float4*)(mm + c0);
    float4 V = *(const float4*)(vv + c0);
    float4 o;
    o.x = G.x * (v0 - M.x) * rsqrtf(V.x + 1e-5f) + B.x;
    o.y = G.y * (v1 - M.y) * rsqrtf(V.y + 1e-5f) + B.y;
    o.z = G.z * (v2 - M.z) * rsqrtf(V.z + 1e-5f) + B.z;
    o.w = G.w * (v3 - M.w) * rsqrtf(V.w + 1e-5f) + B.w;
    *(float4*)(g_h2 + (size_t)w * 192 + c0) = o;
    if (lane < 16) {
        int l = lane * 4, ch = 128 + l;
        float4 cp = *(const float4*)(g_cprod + (size_t)w * 64 + l);
        float4 G2 = *(const float4*)(gg + ch);
        float4 B2 = *(const float4*)(bb + ch);
        float4 M2 = *(const float4*)(mm + ch);
        float4 V2 = *(const float4*)(vv + ch);
        float4 o2;
        o2.x = G2.x * (cp.x - M2.x) * rsqrtf(V2.x + 1e-5f) + B2.x;
        o2.y = G2.y * (cp.y - M2.y) * rsqrtf(V2.y + 1e-5f) + B2.y;
        o2.z = G2.z * (cp.z - M2.z) * rsqrtf(V2.z + 1e-5f) + B2.z;
        o2.w = G2.w * (cp.w - M2.w) * rsqrtf(V2.w + 1e-5f) + B2.w;
        *(float4*)(g_h2 + (size_t)w * 192 + ch) = o2;
    }
}

// ---------------- pooling (batch is sorted) ----------------
__device__ __forceinline__ int lb_batch(const void* batch, int n, long long val) {
    int lo = 0, hi = n;
    while (lo < hi) {
        int mid = (lo + hi) >> 1;
        long long b = g_is64 ? ((const long long*)batch)[mid]
                             : (long long)((const int*)batch)[mid];
        if (b < val) lo = mid + 1; else hi = mid;
    }
    return lo;
}

__global__ void k_pool(const void* batch, int N) {
    int g = blockIdx.x;
    __shared__ int slo, shi;
    if (threadIdx.x == 0) {
        slo = lb_batch(batch, N, (long long)g);
        shi = lb_batch(batch, N, (long long)g + 1);
    }
    __syncthreads();
    int lo = slo, hi = shi;
    int ch = threadIdx.x;  // 192
    float sum = 0.f, mx = -3.402823466e38f;
    for (int n = lo; n < hi; n++) {
        float v = g_h2[(size_t)n * 192 + ch];
        sum += v;
        mx = fmaxf(mx, v);
    }
    int cnt = hi - lo;
    g_pool[g * 384 + ch] = sum / fmaxf((float)cnt, 1.f);
    g_pool[g * 384 + 192 + ch] = (cnt > 0) ? mx : 0.f;
}

// ---------------- head: logits + log_softmax ----------------
__global__ void k_head(const float* __restrict__ w, const float* __restrict__ b,
                       float* __restrict__ out, int G) {
    int t = blockIdx.x * blockDim.x + threadIdx.x;
    int warp = t >> 5, lane = t & 31;
    if (warp >= G) return;
    float lg[6] = {0.f, 0.f, 0.f, 0.f, 0.f, 0.f};
    for (int k = lane; k < 384; k += 32) {
        float gv = g_pool[warp * 384 + k];
#pragma unroll
        for (int j = 0; j < 6; j++) lg[j] += gv * w[k * 6 + j];
    }
#pragma unroll
    for (int off = 16; off; off >>= 1)
#pragma unroll
        for (int j = 0; j < 6; j++) lg[j] += __shfl_xor_sync(0xffffffffu, lg[j], off);
    if (lane == 0) {
        float v[6];
        float mx = -3.402823466e38f;
#pragma unroll
        for (int j = 0; j < 6; j++) { v[j] = lg[j] + b[j]; mx = fmaxf(mx, v[j]); }
        float s = 0.f;
#pragma unroll
        for (int j = 0; j < 6; j++) s += expf(v[j] - mx);
        float lse = mx + logf(s);
#pragma unroll
        for (int j = 0; j < 6; j++) out[warp * 6 + j] = v[j] - lse;
    }
}

// ---------------- launch ----------------
extern "C" void kernel_launch(void* const* d_in, const int* in_sizes, int n_in,
                              void* d_out, int out_size) {
    int base = (n_in >= 30) ? 4 : 3;
    const float* x        = (const float*)d_in[0];
    const void*  ei       = d_in[1];
    const void*  batch    = d_in[2];
    const float* fc11_w   = (const float*)d_in[base + 0];
    const float* fc11_b   = (const float*)d_in[base + 1];
    const float* conv11_w = (const float*)d_in[base + 2];
    const float* conv11_b = (const float*)d_in[base + 3];
    const float* fc12_w   = (const float*)d_in[base + 4];
    const float* fc12_b   = (const float*)d_in[base + 5];
    const float* fc13_w   = (const float*)d_in[base + 6];
    const float* fc13_b   = (const float*)d_in[base + 7];
    const float* bn1_g    = (const float*)d_in[base + 8];
    const float* bn1_b    = (const float*)d_in[base + 9];
    const float* bn1_m    = (const float*)d_in[base + 10];
    const float* bn1_v    = (const float*)d_in[base + 11];
    const float* fc21_w   = (const float*)d_in[base + 12];
    const float* fc21_b   = (const float*)d_in[base + 13];
    const float* conv21_w = (const float*)d_in[base + 14];
    const float* conv21_b = (const float*)d_in[base + 15];
    const float* fc22_w   = (const float*)d_in[base + 16];
    const float* fc22_b   = (const float*)d_in[base + 17];
    const float* fc23_w   = (const float*)d_in[base + 18];
    const float* fc23_b   = (const float*)d_in[base + 19];
    const float* bn2_g    = (const float*)d_in[base + 20];
    const float* bn2_b    = (const float*)d_in[base + 21];
    const float* bn2_m    = (const float*)d_in[base + 22];
    const float* bn2_v    = (const float*)d_in[base + 23];
    const float* fc2_w    = (const float*)d_in[base + 24];
    const float* fc2_b    = (const float*)d_in[base + 25];

    int N = in_sizes[0] / 32;
    int E = in_sizes[1] / 2;
    int G = out_size / 6;
    float* out = (float*)d_out;

    // init (detect + zero + packs + x->bf16), then CSR build
    int initN = N * 32;
    if (initN < 192 * 384) initN = 192 * 384;
    k_init<<<(initN + 255) / 256, 256>>>((const unsigned int*)ei, x,
                                         fc11_w, conv11_w, fc12_w, fc13_w,
                                         fc21_w, conv21_w, fc22_w, fc23_w, N);
    k_hist<<<(E + 255) / 256, 256>>>(ei, E);
    int nb = (N + 1023) / 1024;
    k_scan_a<<<nb, 1024>>>(N);
    k_scan_b<<<1, 64>>>(nb);
    k_scan_c<<<(N + 255) / 256, 256>>>(N, E);
    k_fill<<<(E + 255) / 256, 256>>>(ei, E);

    // block 1: fused aggregate+pack, fused GEMM -> h1
    k_agg1<<<(N * 32 + 255) / 256, 256>>>(x, N);
    dim3 gg((N + 127) / 128, 3);
    k_gemm_tc<1><<<gg, 256>>>(N, fc11_b, conv11_b, fc12_b, fc13_b,
                              bn1_g, bn1_b, bn1_m, bn1_v);

    // block 2: fused GEMM -> lin/m2h/cprod, fused aggregate+epilogue -> h2
    k_gemm_tc<2><<<gg, 256>>>(N, fc21_b, conv21_b, fc22_b, fc23_b,
                              bn2_g, bn2_b, bn2_m, bn2_v);
    k_agg2_ep2<<<(N * 32 + 255) / 256, 256>>>(conv21_b, bn2_g, bn2_b, bn2_m, bn2_v, N);

    // pooling + head
    k_pool<<<G, 192>>>(batch, N);
    k_head<<<(G * 32 + 255) / 256, 256>>>(fc2_w, fc2_b, out, G);
}